// round 8
// baseline (speedup 1.0000x reference)
#include <cuda_runtime.h>

#define BB 32
#define SS 4096
#define CC 768
#define HH 12
#define DD 64
#define NCHUNK 43
#define SCHUNK 96

// ---- scratch (device globals; allocation is forbidden) ----
__device__ float g_qh[HH * DD];                               // scaled probe query
__device__ float g_wk[HH * CC];                               // folded key weights
__device__ float g_sbias[HH];                                 // qh . bk
__device__ float g_z[BB * NCHUNK * HH];                       // per-chunk expsum
__device__ float g_ypart[(size_t)BB * NCHUNK * HH * CC];      // per-chunk partial y
__device__ float g_ctx[BB * CC];                              // context (h,d flattened)

typedef unsigned long long u64;

__device__ __forceinline__ u64 pk2(float a, float b) {
    u64 r; asm("mov.b64 %0,{%1,%2};" : "=l"(r) : "f"(a), "f"(b)); return r;
}
__device__ __forceinline__ float2 up2(u64 v) {
    float2 r; asm("mov.b64 {%0,%1},%2;" : "=f"(r.x), "=f"(r.y) : "l"(v)); return r;
}
__device__ __forceinline__ void ffma2(u64& d, u64 a, u64 b) {
    asm("fma.rn.f32x2 %0,%1,%2,%0;" : "+l"(d) : "l"(a), "l"(b));
}
__device__ __forceinline__ u64 vadd2(u64 a, u64 b) {
    u64 r; asm("add.rn.f32x2 %0,%1,%2;" : "=l"(r) : "l"(a), "l"(b)); return r;
}

// ================= prep 1: qh = (probe @ Wq + bq)/8 =================
__global__ __launch_bounds__(256) void k_prep_qh(const float* __restrict__ probe,
                                                 const float* __restrict__ Wq,
                                                 const float* __restrict__ bq) {
    int h = blockIdx.x, t = threadIdx.x;
    __shared__ float red[4][DD];
    int d = t & 63, part = t >> 6;
    float a = 0.f;
    #pragma unroll 8
    for (int c = part; c < CC; c += 4)
        a = fmaf(probe[c], Wq[(size_t)c * CC + h * DD + d], a);
    red[part][d] = a;
    __syncthreads();
    if (t < DD)
        g_qh[h * DD + t] = (red[0][t] + red[1][t] + red[2][t] + red[3][t] + bq[h * DD + t]) * 0.125f;
}

// ================= prep 2: wk[h,c] = sum_d Wk[c,h,d]*qh[h,d] =================
__global__ __launch_bounds__(256) void k_prep_wk(const float* __restrict__ Wk) {
    int h = blockIdx.x, t = threadIdx.x;
    __shared__ float qs[DD];
    if (t < DD) qs[t] = g_qh[h * DD + t];
    __syncthreads();
    for (int c = t; c < CC; c += 256) {
        const float4* wr = (const float4*)(Wk + (size_t)c * CC + h * DD);
        float s = 0.f;
        #pragma unroll
        for (int j = 0; j < DD / 4; j++) {
            float4 wv = wr[j];
            const float4 qv = *(const float4*)(qs + 4 * j);
            s += wv.x * qv.x + wv.y * qv.y + wv.z * qv.z + wv.w * qv.w;
        }
        g_wk[h * CC + c] = s;
    }
}

// ================= prep 3: sbias[h] = qh[h,:].bk[h,:] =================
__global__ __launch_bounds__(384) void k_prep_sb(const float* __restrict__ bk) {
    int t = threadIdx.x, h = t >> 5, lane = t & 31;
    float a = g_qh[h * DD + lane] * bk[h * DD + lane]
            + g_qh[h * DD + 32 + lane] * bk[h * DD + 32 + lane];
    #pragma unroll
    for (int o = 16; o; o >>= 1) a += __shfl_xor_sync(~0u, a, o);
    if (lane == 0) g_sbias[h] = a;
}

// ================= fused: scores -> exp -> weighted accumulate (launch #4) ===========
// 384 threads, 2 blocks/SM. Phase 1: warp pairs split heads 6+6, 4 rows/thread.
// Phase 2: 4 cols/thread, 48-row halves; p stored as PLAIN floats, loaded as
// float4 (4 rows per LDS.128) and duplicated into f32x2 via MOVs (alu pipe),
// halving the smem delivery bytes vs duplicated-u64 storage.
__global__ __launch_bounds__(384, 2) void k_fused(const float* __restrict__ x) {
    __shared__ __align__(16) float uS[HH * CC];      // wk (phase 1) / y stage (phase 2)
    __shared__ __align__(16) float sc[HH][SCHUNK];   // exp(score), plain f32, 4.5 KB
    __shared__ float zsh[HH];
    __shared__ float sbs[HH];

    int t = threadIdx.x, ch = blockIdx.x, b = blockIdx.y;
    int s0 = ch * SCHUNK;
    for (int i = t; i < HH * CC; i += 384) uS[i] = g_wk[i];
    if (t < HH) { sbs[t] = g_sbias[t]; zsh[t] = 0.f; }
    __syncthreads();

    int lane = t & 31, w = t >> 5, g = lane >> 3, q = lane & 7;
    const float* xb = x + (size_t)b * SS * CC;

    // ---- phase 1 ----
    {
        int p = w >> 1, h0 = (w & 1) * 6;
        int lbase = p * 16 + g;                        // local row = lbase + 4k
        const ulonglong2* xr[4];
        #pragma unroll
        for (int k = 0; k < 4; k++) {
            int row = s0 + lbase + 4 * k;
            int rc = row < SS ? row : SS - 1;
            xr[k] = (const ulonglong2*)(xb + (size_t)rc * CC) + q;
        }
        const ulonglong2* wq = (const ulonglong2*)uS + h0 * (CC / 4) + q;

        u64 acc[6][4];
        #pragma unroll
        for (int i = 0; i < 6; i++)
            #pragma unroll
            for (int k = 0; k < 4; k++) acc[i][k] = 0ull;

        #pragma unroll 4
        for (int j = 0; j < 24; j++) {
            ulonglong2 xv0 = xr[0][j * 8];
            ulonglong2 xv1 = xr[1][j * 8];
            ulonglong2 xv2 = xr[2][j * 8];
            ulonglong2 xv3 = xr[3][j * 8];
            #pragma unroll
            for (int i = 0; i < 6; i++) {
                ulonglong2 wv = wq[i * (CC / 4) + j * 8];
                ffma2(acc[i][0], xv0.x, wv.x); ffma2(acc[i][0], xv0.y, wv.y);
                ffma2(acc[i][1], xv1.x, wv.x); ffma2(acc[i][1], xv1.y, wv.y);
                ffma2(acc[i][2], xv2.x, wv.x); ffma2(acc[i][2], xv2.y, wv.y);
                ffma2(acc[i][3], xv3.x, wv.x); ffma2(acc[i][3], xv3.y, wv.y);
            }
        }
        #pragma unroll
        for (int i = 0; i < 6; i++) {
            float zt = 0.f;
            #pragma unroll
            for (int k = 0; k < 4; k++) {
                u64 v = acc[i][k];
                v = vadd2(v, __shfl_xor_sync(0xffffffffu, v, 4));
                v = vadd2(v, __shfl_xor_sync(0xffffffffu, v, 2));
                v = vadd2(v, __shfl_xor_sync(0xffffffffu, v, 1));
                if (q == 0) {
                    int lr = lbase + 4 * k;
                    float2 f = up2(v);
                    float e = (s0 + lr < SS) ? __expf(f.x + f.y + sbs[h0 + i]) : 0.f;
                    sc[h0 + i][lr] = e;
                    zt += e;
                }
            }
            float zq = (q == 0) ? zt : 0.f;
            zq += __shfl_xor_sync(0xffffffffu, zq, 8);
            zq += __shfl_xor_sync(0xffffffffu, zq, 16);
            if (lane == 0) atomicAdd(&zsh[h0 + i], zq);
        }
    }
    __syncthreads();
    if (t < HH) g_z[(b * NCHUNK + ch) * HH + t] = zsh[t];

    // ---- phase 2: y_part = sum_s p[h][s] * x[s,:] ----
    int half = t / 192, u = t - half * 192;            // cols 4u..4u+3
    int bs = half * 48;
    int rem = SS - (s0 + bs);
    int slim = rem < 0 ? 0 : (rem > 48 ? 48 : rem);    // multiple of 16
    const float* xp = xb + (size_t)(s0 + bs) * CC + 4 * u;

    u64 acc2[HH][2];
    #pragma unroll
    for (int h = 0; h < HH; h++) { acc2[h][0] = 0ull; acc2[h][1] = 0ull; }

    for (int s4 = 0; s4 < slim / 4; s4++) {
        ulonglong2 xv0 = *(const ulonglong2*)(xp + (size_t)(4 * s4)     * CC);
        ulonglong2 xv1 = *(const ulonglong2*)(xp + (size_t)(4 * s4 + 1) * CC);
        ulonglong2 xv2 = *(const ulonglong2*)(xp + (size_t)(4 * s4 + 2) * CC);
        ulonglong2 xv3 = *(const ulonglong2*)(xp + (size_t)(4 * s4 + 3) * CC);
        #pragma unroll
        for (int h = 0; h < HH; h++) {
            float4 pv = *(const float4*)&sc[h][bs + 4 * s4];
            u64 p0 = pk2(pv.x, pv.x), p1 = pk2(pv.y, pv.y);
            u64 p2 = pk2(pv.z, pv.z), p3 = pk2(pv.w, pv.w);
            ffma2(acc2[h][0], p0, xv0.x); ffma2(acc2[h][1], p0, xv0.y);
            ffma2(acc2[h][0], p1, xv1.x); ffma2(acc2[h][1], p1, xv1.y);
            ffma2(acc2[h][0], p2, xv2.x); ffma2(acc2[h][1], p2, xv2.y);
            ffma2(acc2[h][0], p3, xv3.x); ffma2(acc2[h][1], p3, xv3.y);
        }
    }

    // half 1 stages into uS (wk no longer needed); half 0 merges and writes
    __syncthreads();
    if (half == 1) {
        #pragma unroll
        for (int h = 0; h < HH; h++) {
            float2 l0 = up2(acc2[h][0]), l1 = up2(acc2[h][1]);
            *(float4*)(uS + h * CC + 4 * u) = make_float4(l0.x, l0.y, l1.x, l1.y);
        }
    }
    __syncthreads();
    if (half == 0) {
        float* yp = g_ypart + ((size_t)(b * NCHUNK + ch)) * (HH * CC);
        #pragma unroll
        for (int h = 0; h < HH; h++) {
            float2 l0 = up2(acc2[h][0]), l1 = up2(acc2[h][1]);
            float4 sv = *(const float4*)(uS + h * CC + 4 * u);
            *(float4*)(yp + h * CC + 4 * u) =
                make_float4(l0.x + sv.x, l0.y + sv.y, l1.x + sv.z, l1.y + sv.w);
        }
    }
}

// ================= combine + ctx: y = sum(ypart)/Z, ctx = y @ Wv + bv =================
__global__ __launch_bounds__(256) void k_combctx(const float* __restrict__ Wv,
                                                 const float* __restrict__ bv) {
    int b = blockIdx.x, h = blockIdx.y, t = threadIdx.x;
    __shared__ float ys[CC];
    __shared__ float red[4][DD];
    __shared__ float invZ_s;

    if (t < 32) {
        float z = 0.f;
        for (int c2 = t; c2 < NCHUNK; c2 += 32) z += g_z[(b * NCHUNK + c2) * HH + h];
        #pragma unroll
        for (int o = 16; o; o >>= 1) z += __shfl_xor_sync(~0u, z, o);
        if (t == 0) invZ_s = 1.f / z;
    }
    __syncthreads();
    float invZ = invZ_s;

    #pragma unroll
    for (int i = 0; i < 3; i++) {
        int c = t + 256 * i;
        const float* base = g_ypart + (size_t)b * NCHUNK * HH * CC + h * CC + c;
        float a[8];
        #pragma unroll
        for (int k = 0; k < 8; k++) a[k] = 0.f;
        for (int chn = 0; chn + 8 <= NCHUNK; chn += 8) {
            #pragma unroll
            for (int k = 0; k < 8; k++)
                a[k] += base[(size_t)(chn + k) * HH * CC];
        }
        #pragma unroll
        for (int k = 0; k < (NCHUNK & 7); k++)
            a[k] += base[(size_t)((NCHUNK & ~7) + k) * HH * CC];
        float s = ((a[0] + a[1]) + (a[2] + a[3])) + ((a[4] + a[5]) + (a[6] + a[7]));
        ys[c] = s * invZ;
    }
    __syncthreads();

    int d = t & 63, part = t >> 6;
    const float* wp = Wv + h * DD + d;
    float a0 = 0.f, a1 = 0.f;
    #pragma unroll 8
    for (int c = part; c < CC; c += 8) {
        a0 = fmaf(ys[c],     wp[(size_t)c * CC],       a0);
        a1 = fmaf(ys[c + 4], wp[(size_t)(c + 4) * CC], a1);
    }
    red[part][d] = a0 + a1;
    __syncthreads();
    if (t < DD)
        g_ctx[b * CC + h * DD + t] =
            red[0][t] + red[1][t] + red[2][t] + red[3][t] + bv[h * DD + t];
}

// ================= out: out[b,c'] = ctx[b,:] @ Wo + bo =================
__global__ __launch_bounds__(192) void k_out(const float* __restrict__ Wo,
                                             const float* __restrict__ bo,
                                             float* __restrict__ out) {
    int b = blockIdx.x, part = blockIdx.y, t = threadIdx.x;
    __shared__ float cs[CC];
    for (int i = t; i < CC; i += 192) cs[i] = g_ctx[b * CC + i];
    __syncthreads();
    int cp = part * 192 + t;
    const float* wp = Wo + cp;
    float a[8];
    #pragma unroll
    for (int k = 0; k < 8; k++) a[k] = 0.f;
    #pragma unroll 4
    for (int o = 0; o < CC; o += 8) {
        #pragma unroll
        for (int k = 0; k < 8; k++)
            a[k] = fmaf(cs[o + k], wp[(size_t)(o + k) * CC], a[k]);
    }
    out[(size_t)b * CC + cp] =
        ((a[0] + a[1]) + (a[2] + a[3])) + ((a[4] + a[5]) + (a[6] + a[7])) + bo[cp];
}

extern "C" void kernel_launch(void* const* d_in, const int* in_sizes, int n_in,
                              void* d_out, int out_size) {
    const float* x     = (const float*)d_in[0];
    const float* probe = (const float*)d_in[1];
    const float* Wq    = (const float*)d_in[2];
    const float* bq    = (const float*)d_in[3];
    const float* Wk    = (const float*)d_in[4];
    const float* bk    = (const float*)d_in[5];
    const float* Wv    = (const float*)d_in[6];
    const float* bv    = (const float*)d_in[7];
    const float* Wo    = (const float*)d_in[8];
    const float* bo    = (const float*)d_in[9];
    float* out = (float*)d_out;

    k_prep_qh<<<HH, 256>>>(probe, Wq, bq);          // #1
    k_prep_wk<<<HH, 256>>>(Wk);                     // #2
    k_prep_sb<<<1, 384>>>(bk);                      // #3
    k_fused<<<dim3(NCHUNK, BB), 384>>>(x);          // #4  <- profiled
    k_combctx<<<dim3(BB, HH), 256>>>(Wv, bv);       // #5
    k_out<<<dim3(BB, 4), 192>>>(Wo, bo, out);       // #6
}

// round 9
// speedup vs baseline: 1.3721x; 1.3721x over previous
#include <cuda_runtime.h>

#define BB 32
#define SS 4096
#define CC 768
#define HH 12
#define DD 64
#define NCHUNK 43
#define SCHUNK 96

// ---- scratch (device globals; allocation is forbidden) ----
__device__ float g_qh[HH * DD];                               // scaled probe query
__device__ float g_wk[HH * CC];                               // folded key weights
__device__ float g_sbias[HH];                                 // qh . bk
__device__ float g_z[BB * NCHUNK * HH];                       // per-chunk expsum
__device__ float g_ypart[(size_t)BB * NCHUNK * HH * CC];      // per-chunk partial y
__device__ float g_ctx[BB * CC];                              // context (h,d flattened)

typedef unsigned long long u64;

__device__ __forceinline__ u64 pk2(float a, float b) {
    u64 r; asm("mov.b64 %0,{%1,%2};" : "=l"(r) : "f"(a), "f"(b)); return r;
}
__device__ __forceinline__ float2 up2(u64 v) {
    float2 r; asm("mov.b64 {%0,%1},%2;" : "=f"(r.x), "=f"(r.y) : "l"(v)); return r;
}
__device__ __forceinline__ void ffma2(u64& d, u64 a, u64 b) {
    asm("fma.rn.f32x2 %0,%1,%2,%0;" : "+l"(d) : "l"(a), "l"(b));
}
__device__ __forceinline__ u64 vadd2(u64 a, u64 b) {
    u64 r; asm("add.rn.f32x2 %0,%1,%2;" : "=l"(r) : "l"(a), "l"(b)); return r;
}

// ================= prep 1: qh = (probe @ Wq + bq)/8 =================
__global__ __launch_bounds__(256) void k_prep_qh(const float* __restrict__ probe,
                                                 const float* __restrict__ Wq,
                                                 const float* __restrict__ bq) {
    int h = blockIdx.x, t = threadIdx.x;
    __shared__ float red[4][DD];
    int d = t & 63, part = t >> 6;
    float a = 0.f;
    #pragma unroll 8
    for (int c = part; c < CC; c += 4)
        a = fmaf(probe[c], Wq[(size_t)c * CC + h * DD + d], a);
    red[part][d] = a;
    __syncthreads();
    if (t < DD)
        g_qh[h * DD + t] = (red[0][t] + red[1][t] + red[2][t] + red[3][t] + bq[h * DD + t]) * 0.125f;
}

// ================= prep 2: wk[h,c] = sum_d Wk[c,h,d]*qh[h,d] =================
__global__ __launch_bounds__(256) void k_prep_wk(const float* __restrict__ Wk) {
    int h = blockIdx.x, t = threadIdx.x;
    __shared__ float qs[DD];
    if (t < DD) qs[t] = g_qh[h * DD + t];
    __syncthreads();
    for (int c = t; c < CC; c += 256) {
        const float4* wr = (const float4*)(Wk + (size_t)c * CC + h * DD);
        float s = 0.f;
        #pragma unroll
        for (int j = 0; j < DD / 4; j++) {
            float4 wv = wr[j];
            const float4 qv = *(const float4*)(qs + 4 * j);
            s += wv.x * qv.x + wv.y * qv.y + wv.z * qv.z + wv.w * qv.w;
        }
        g_wk[h * CC + c] = s;
    }
}

// ================= prep 3: sbias[h] = qh[h,:].bk[h,:] =================
__global__ __launch_bounds__(384) void k_prep_sb(const float* __restrict__ bk) {
    int t = threadIdx.x, h = t >> 5, lane = t & 31;
    float a = g_qh[h * DD + lane] * bk[h * DD + lane]
            + g_qh[h * DD + 32 + lane] * bk[h * DD + 32 + lane];
    #pragma unroll
    for (int o = 16; o; o >>= 1) a += __shfl_xor_sync(~0u, a, o);
    if (lane == 0) g_sbias[h] = a;
}

// ================= fused: scores -> exp -> weighted accumulate (launch #4) ===========
// (identical to round-8 version: measured 253.7 us)
__global__ __launch_bounds__(384, 2) void k_fused(const float* __restrict__ x) {
    __shared__ __align__(16) float uS[HH * CC];      // wk (phase 1) / y stage (phase 2)
    __shared__ __align__(16) float sc[HH][SCHUNK];   // exp(score), plain f32, 4.5 KB
    __shared__ float zsh[HH];
    __shared__ float sbs[HH];

    int t = threadIdx.x, ch = blockIdx.x, b = blockIdx.y;
    int s0 = ch * SCHUNK;
    for (int i = t; i < HH * CC; i += 384) uS[i] = g_wk[i];
    if (t < HH) { sbs[t] = g_sbias[t]; zsh[t] = 0.f; }
    __syncthreads();

    int lane = t & 31, w = t >> 5, g = lane >> 3, q = lane & 7;
    const float* xb = x + (size_t)b * SS * CC;

    // ---- phase 1 ----
    {
        int p = w >> 1, h0 = (w & 1) * 6;
        int lbase = p * 16 + g;                        // local row = lbase + 4k
        const ulonglong2* xr[4];
        #pragma unroll
        for (int k = 0; k < 4; k++) {
            int row = s0 + lbase + 4 * k;
            int rc = row < SS ? row : SS - 1;
            xr[k] = (const ulonglong2*)(xb + (size_t)rc * CC) + q;
        }
        const ulonglong2* wq = (const ulonglong2*)uS + h0 * (CC / 4) + q;

        u64 acc[6][4];
        #pragma unroll
        for (int i = 0; i < 6; i++)
            #pragma unroll
            for (int k = 0; k < 4; k++) acc[i][k] = 0ull;

        #pragma unroll 4
        for (int j = 0; j < 24; j++) {
            ulonglong2 xv0 = xr[0][j * 8];
            ulonglong2 xv1 = xr[1][j * 8];
            ulonglong2 xv2 = xr[2][j * 8];
            ulonglong2 xv3 = xr[3][j * 8];
            #pragma unroll
            for (int i = 0; i < 6; i++) {
                ulonglong2 wv = wq[i * (CC / 4) + j * 8];
                ffma2(acc[i][0], xv0.x, wv.x); ffma2(acc[i][0], xv0.y, wv.y);
                ffma2(acc[i][1], xv1.x, wv.x); ffma2(acc[i][1], xv1.y, wv.y);
                ffma2(acc[i][2], xv2.x, wv.x); ffma2(acc[i][2], xv2.y, wv.y);
                ffma2(acc[i][3], xv3.x, wv.x); ffma2(acc[i][3], xv3.y, wv.y);
            }
        }
        #pragma unroll
        for (int i = 0; i < 6; i++) {
            float zt = 0.f;
            #pragma unroll
            for (int k = 0; k < 4; k++) {
                u64 v = acc[i][k];
                v = vadd2(v, __shfl_xor_sync(0xffffffffu, v, 4));
                v = vadd2(v, __shfl_xor_sync(0xffffffffu, v, 2));
                v = vadd2(v, __shfl_xor_sync(0xffffffffu, v, 1));
                if (q == 0) {
                    int lr = lbase + 4 * k;
                    float2 f = up2(v);
                    float e = (s0 + lr < SS) ? __expf(f.x + f.y + sbs[h0 + i]) : 0.f;
                    sc[h0 + i][lr] = e;
                    zt += e;
                }
            }
            float zq = (q == 0) ? zt : 0.f;
            zq += __shfl_xor_sync(0xffffffffu, zq, 8);
            zq += __shfl_xor_sync(0xffffffffu, zq, 16);
            if (lane == 0) atomicAdd(&zsh[h0 + i], zq);
        }
    }
    __syncthreads();
    if (t < HH) g_z[(b * NCHUNK + ch) * HH + t] = zsh[t];

    // ---- phase 2: y_part = sum_s p[h][s] * x[s,:] ----
    int half = t / 192, u = t - half * 192;            // cols 4u..4u+3
    int bs = half * 48;
    int rem = SS - (s0 + bs);
    int slim = rem < 0 ? 0 : (rem > 48 ? 48 : rem);    // multiple of 16
    const float* xp = xb + (size_t)(s0 + bs) * CC + 4 * u;

    u64 acc2[HH][2];
    #pragma unroll
    for (int h = 0; h < HH; h++) { acc2[h][0] = 0ull; acc2[h][1] = 0ull; }

    for (int s4 = 0; s4 < slim / 4; s4++) {
        ulonglong2 xv0 = *(const ulonglong2*)(xp + (size_t)(4 * s4)     * CC);
        ulonglong2 xv1 = *(const ulonglong2*)(xp + (size_t)(4 * s4 + 1) * CC);
        ulonglong2 xv2 = *(const ulonglong2*)(xp + (size_t)(4 * s4 + 2) * CC);
        ulonglong2 xv3 = *(const ulonglong2*)(xp + (size_t)(4 * s4 + 3) * CC);
        #pragma unroll
        for (int h = 0; h < HH; h++) {
            float4 pv = *(const float4*)&sc[h][bs + 4 * s4];
            u64 p0 = pk2(pv.x, pv.x), p1 = pk2(pv.y, pv.y);
            u64 p2 = pk2(pv.z, pv.z), p3 = pk2(pv.w, pv.w);
            ffma2(acc2[h][0], p0, xv0.x); ffma2(acc2[h][1], p0, xv0.y);
            ffma2(acc2[h][0], p1, xv1.x); ffma2(acc2[h][1], p1, xv1.y);
            ffma2(acc2[h][0], p2, xv2.x); ffma2(acc2[h][1], p2, xv2.y);
            ffma2(acc2[h][0], p3, xv3.x); ffma2(acc2[h][1], p3, xv3.y);
        }
    }

    // half 1 stages into uS (wk no longer needed); half 0 merges and writes
    __syncthreads();
    if (half == 1) {
        #pragma unroll
        for (int h = 0; h < HH; h++) {
            float2 l0 = up2(acc2[h][0]), l1 = up2(acc2[h][1]);
            *(float4*)(uS + h * CC + 4 * u) = make_float4(l0.x, l0.y, l1.x, l1.y);
        }
    }
    __syncthreads();
    if (half == 0) {
        float* yp = g_ypart + ((size_t)(b * NCHUNK + ch)) * (HH * CC);
        #pragma unroll
        for (int h = 0; h < HH; h++) {
            float2 l0 = up2(acc2[h][0]), l1 = up2(acc2[h][1]);
            float4 sv = *(const float4*)(uS + h * CC + 4 * u);
            *(float4*)(yp + h * CC + 4 * u) =
                make_float4(l0.x + sv.x, l0.y + sv.y, l1.x + sv.z, l1.y + sv.w);
        }
    }
}

// ================= combine + ctx (exact round-7 version, measured fast) =================
__global__ __launch_bounds__(256) void k_combctx(const float* __restrict__ Wv,
                                                 const float* __restrict__ bv) {
    int b = blockIdx.x, h = blockIdx.y, t = threadIdx.x;
    __shared__ float ys[CC];
    __shared__ float red[4][DD];
    __shared__ float invZ_s;

    if (t < 32) {
        float z = 0.f;
        for (int c2 = t; c2 < NCHUNK; c2 += 32) z += g_z[(b * NCHUNK + c2) * HH + h];
        #pragma unroll
        for (int o = 16; o; o >>= 1) z += __shfl_xor_sync(~0u, z, o);
        if (t == 0) invZ_s = 1.f / z;
    }
    __syncthreads();
    float invZ = invZ_s;

    #pragma unroll
    for (int i = 0; i < 3; i++) {
        int c = t + 256 * i;
        const float* base = g_ypart + (size_t)b * NCHUNK * HH * CC + h * CC + c;
        float a0 = 0.f, a1 = 0.f, a2 = 0.f, a3 = 0.f;
        #pragma unroll 4
        for (int chn = 0; chn < NCHUNK - 3; chn += 4) {
            a0 += base[(size_t)chn * HH * CC];
            a1 += base[(size_t)(chn + 1) * HH * CC];
            a2 += base[(size_t)(chn + 2) * HH * CC];
            a3 += base[(size_t)(chn + 3) * HH * CC];
        }
        for (int chn = NCHUNK & ~3; chn < NCHUNK; chn++)
            a0 += base[(size_t)chn * HH * CC];
        ys[c] = ((a0 + a1) + (a2 + a3)) * invZ;
    }
    __syncthreads();

    int d = t & 63, part = t >> 6;
    const float* wp = Wv + h * DD + d;
    float a0 = 0.f, a1 = 0.f;
    #pragma unroll 8
    for (int c = part; c < CC; c += 8) {
        a0 = fmaf(ys[c],     wp[(size_t)c * CC],       a0);
        a1 = fmaf(ys[c + 4], wp[(size_t)(c + 4) * CC], a1);
    }
    red[part][d] = a0 + a1;
    __syncthreads();
    if (t < DD)
        g_ctx[b * CC + h * DD + t] =
            red[0][t] + red[1][t] + red[2][t] + red[3][t] + bv[h * DD + t];
}

// ================= out (exact round-7 version) =================
__global__ __launch_bounds__(192) void k_out(const float* __restrict__ Wo,
                                             const float* __restrict__ bo,
                                             float* __restrict__ out) {
    int b = blockIdx.x, part = blockIdx.y, t = threadIdx.x;
    __shared__ float cs[CC];
    for (int i = t; i < CC; i += 192) cs[i] = g_ctx[b * CC + i];
    __syncthreads();
    int cp = part * 192 + t;
    const float* wp = Wo + cp;
    float a0 = 0.f, a1 = 0.f, a2 = 0.f, a3 = 0.f;
    #pragma unroll 8
    for (int o = 0; o < CC; o += 4) {
        a0 = fmaf(cs[o],     wp[(size_t)o * CC],       a0);
        a1 = fmaf(cs[o + 1], wp[(size_t)(o + 1) * CC], a1);
        a2 = fmaf(cs[o + 2], wp[(size_t)(o + 2) * CC], a2);
        a3 = fmaf(cs[o + 3], wp[(size_t)(o + 3) * CC], a3);
    }
    out[(size_t)b * CC + cp] = (a0 + a1) + (a2 + a3) + bo[cp];
}

extern "C" void kernel_launch(void* const* d_in, const int* in_sizes, int n_in,
                              void* d_out, int out_size) {
    const float* x     = (const float*)d_in[0];
    const float* probe = (const float*)d_in[1];
    const float* Wq    = (const float*)d_in[2];
    const float* bq    = (const float*)d_in[3];
    const float* Wk    = (const float*)d_in[4];
    const float* bk    = (const float*)d_in[5];
    const float* Wv    = (const float*)d_in[6];
    const float* bv    = (const float*)d_in[7];
    const float* Wo    = (const float*)d_in[8];
    const float* bo    = (const float*)d_in[9];
    float* out = (float*)d_out;

    k_prep_qh<<<HH, 256>>>(probe, Wq, bq);          // #1
    k_prep_wk<<<HH, 256>>>(Wk);                     // #2
    k_prep_sb<<<1, 384>>>(bk);                      // #3
    k_fused<<<dim3(NCHUNK, BB), 384>>>(x);          // #4  <- profiled
    k_combctx<<<dim3(BB, HH), 256>>>(Wv, bv);       // #5
    k_out<<<dim3(BB, 4), 192>>>(Wo, bo, out);       // #6
}

// round 10
// speedup vs baseline: 1.3882x; 1.0118x over previous
#include <cuda_runtime.h>

#define BB 32
#define SS 4096
#define CC 768
#define HH 12
#define DD 64
#define NCHUNK 43
#define SCHUNK 96

// ---- scratch (device globals; allocation is forbidden) ----
__device__ float g_qh[HH * DD];                               // scaled probe query
__device__ float g_wk[HH * CC];                               // folded key weights
__device__ float g_sbias[HH];                                 // qh . bk
__device__ float g_z[BB * NCHUNK * HH];                       // per-chunk expsum
__device__ float g_ypart[(size_t)BB * NCHUNK * HH * CC];      // per-chunk partial y
__device__ float g_ctx[BB * CC];                              // context (h,d flattened)

typedef unsigned long long u64;

__device__ __forceinline__ u64 pk2(float a, float b) {
    u64 r; asm("mov.b64 %0,{%1,%2};" : "=l"(r) : "f"(a), "f"(b)); return r;
}
__device__ __forceinline__ float2 up2(u64 v) {
    float2 r; asm("mov.b64 {%0,%1},%2;" : "=f"(r.x), "=f"(r.y) : "l"(v)); return r;
}
__device__ __forceinline__ void ffma2(u64& d, u64 a, u64 b) {
    asm("fma.rn.f32x2 %0,%1,%2,%0;" : "+l"(d) : "l"(a), "l"(b));
}
__device__ __forceinline__ u64 vadd2(u64 a, u64 b) {
    u64 r; asm("add.rn.f32x2 %0,%1,%2;" : "=l"(r) : "l"(a), "l"(b)); return r;
}

// ================= prep 1: qh = (probe @ Wq + bq)/8 =================
__global__ __launch_bounds__(256) void k_prep_qh(const float* __restrict__ probe,
                                                 const float* __restrict__ Wq,
                                                 const float* __restrict__ bq) {
    int h = blockIdx.x, t = threadIdx.x;
    __shared__ float red[4][DD];
    int d = t & 63, part = t >> 6;
    float a = 0.f;
    #pragma unroll 8
    for (int c = part; c < CC; c += 4)
        a = fmaf(probe[c], Wq[(size_t)c * CC + h * DD + d], a);
    red[part][d] = a;
    __syncthreads();
    if (t < DD)
        g_qh[h * DD + t] = (red[0][t] + red[1][t] + red[2][t] + red[3][t] + bq[h * DD + t]) * 0.125f;
}

// ================= prep 2: wk[h,c] = sum_d Wk[c,h,d]*qh[h,d] =================
__global__ __launch_bounds__(256) void k_prep_wk(const float* __restrict__ Wk) {
    int h = blockIdx.x, t = threadIdx.x;
    __shared__ float qs[DD];
    if (t < DD) qs[t] = g_qh[h * DD + t];
    __syncthreads();
    for (int c = t; c < CC; c += 256) {
        const float4* wr = (const float4*)(Wk + (size_t)c * CC + h * DD);
        float s = 0.f;
        #pragma unroll
        for (int j = 0; j < DD / 4; j++) {
            float4 wv = wr[j];
            const float4 qv = *(const float4*)(qs + 4 * j);
            s += wv.x * qv.x + wv.y * qv.y + wv.z * qv.z + wv.w * qv.w;
        }
        g_wk[h * CC + c] = s;
    }
}

// ================= prep 3: sbias[h] = qh[h,:].bk[h,:] =================
__global__ __launch_bounds__(384) void k_prep_sb(const float* __restrict__ bk) {
    int t = threadIdx.x, h = t >> 5, lane = t & 31;
    float a = g_qh[h * DD + lane] * bk[h * DD + lane]
            + g_qh[h * DD + 32 + lane] * bk[h * DD + 32 + lane];
    #pragma unroll
    for (int o = 16; o; o >>= 1) a += __shfl_xor_sync(~0u, a, o);
    if (lane == 0) g_sbias[h] = a;
}

// ================= fused: scores -> exp -> weighted accumulate (launch #4) ===========
// (identical to round-8 version: measured 253.7 us)
__global__ __launch_bounds__(384, 2) void k_fused(const float* __restrict__ x) {
    __shared__ __align__(16) float uS[HH * CC];      // wk (phase 1) / y stage (phase 2)
    __shared__ __align__(16) float sc[HH][SCHUNK];   // exp(score), plain f32, 4.5 KB
    __shared__ float zsh[HH];
    __shared__ float sbs[HH];

    int t = threadIdx.x, ch = blockIdx.x, b = blockIdx.y;
    int s0 = ch * SCHUNK;
    for (int i = t; i < HH * CC; i += 384) uS[i] = g_wk[i];
    if (t < HH) { sbs[t] = g_sbias[t]; zsh[t] = 0.f; }
    __syncthreads();

    int lane = t & 31, w = t >> 5, g = lane >> 3, q = lane & 7;
    const float* xb = x + (size_t)b * SS * CC;

    // ---- phase 1 ----
    {
        int p = w >> 1, h0 = (w & 1) * 6;
        int lbase = p * 16 + g;                        // local row = lbase + 4k
        const ulonglong2* xr[4];
        #pragma unroll
        for (int k = 0; k < 4; k++) {
            int row = s0 + lbase + 4 * k;
            int rc = row < SS ? row : SS - 1;
            xr[k] = (const ulonglong2*)(xb + (size_t)rc * CC) + q;
        }
        const ulonglong2* wq = (const ulonglong2*)uS + h0 * (CC / 4) + q;

        u64 acc[6][4];
        #pragma unroll
        for (int i = 0; i < 6; i++)
            #pragma unroll
            for (int k = 0; k < 4; k++) acc[i][k] = 0ull;

        #pragma unroll 4
        for (int j = 0; j < 24; j++) {
            ulonglong2 xv0 = xr[0][j * 8];
            ulonglong2 xv1 = xr[1][j * 8];
            ulonglong2 xv2 = xr[2][j * 8];
            ulonglong2 xv3 = xr[3][j * 8];
            #pragma unroll
            for (int i = 0; i < 6; i++) {
                ulonglong2 wv = wq[i * (CC / 4) + j * 8];
                ffma2(acc[i][0], xv0.x, wv.x); ffma2(acc[i][0], xv0.y, wv.y);
                ffma2(acc[i][1], xv1.x, wv.x); ffma2(acc[i][1], xv1.y, wv.y);
                ffma2(acc[i][2], xv2.x, wv.x); ffma2(acc[i][2], xv2.y, wv.y);
                ffma2(acc[i][3], xv3.x, wv.x); ffma2(acc[i][3], xv3.y, wv.y);
            }
        }
        #pragma unroll
        for (int i = 0; i < 6; i++) {
            float zt = 0.f;
            #pragma unroll
            for (int k = 0; k < 4; k++) {
                u64 v = acc[i][k];
                v = vadd2(v, __shfl_xor_sync(0xffffffffu, v, 4));
                v = vadd2(v, __shfl_xor_sync(0xffffffffu, v, 2));
                v = vadd2(v, __shfl_xor_sync(0xffffffffu, v, 1));
                if (q == 0) {
                    int lr = lbase + 4 * k;
                    float2 f = up2(v);
                    float e = (s0 + lr < SS) ? __expf(f.x + f.y + sbs[h0 + i]) : 0.f;
                    sc[h0 + i][lr] = e;
                    zt += e;
                }
            }
            float zq = (q == 0) ? zt : 0.f;
            zq += __shfl_xor_sync(0xffffffffu, zq, 8);
            zq += __shfl_xor_sync(0xffffffffu, zq, 16);
            if (lane == 0) atomicAdd(&zsh[h0 + i], zq);
        }
    }
    __syncthreads();
    if (t < HH) g_z[(b * NCHUNK + ch) * HH + t] = zsh[t];

    // ---- phase 2: y_part = sum_s p[h][s] * x[s,:] ----
    int half = t / 192, u = t - half * 192;            // cols 4u..4u+3
    int bs = half * 48;
    int rem = SS - (s0 + bs);
    int slim = rem < 0 ? 0 : (rem > 48 ? 48 : rem);    // multiple of 16
    const float* xp = xb + (size_t)(s0 + bs) * CC + 4 * u;

    u64 acc2[HH][2];
    #pragma unroll
    for (int h = 0; h < HH; h++) { acc2[h][0] = 0ull; acc2[h][1] = 0ull; }

    for (int s4 = 0; s4 < slim / 4; s4++) {
        ulonglong2 xv0 = *(const ulonglong2*)(xp + (size_t)(4 * s4)     * CC);
        ulonglong2 xv1 = *(const ulonglong2*)(xp + (size_t)(4 * s4 + 1) * CC);
        ulonglong2 xv2 = *(const ulonglong2*)(xp + (size_t)(4 * s4 + 2) * CC);
        ulonglong2 xv3 = *(const ulonglong2*)(xp + (size_t)(4 * s4 + 3) * CC);
        #pragma unroll
        for (int h = 0; h < HH; h++) {
            float4 pv = *(const float4*)&sc[h][bs + 4 * s4];
            u64 p0 = pk2(pv.x, pv.x), p1 = pk2(pv.y, pv.y);
            u64 p2 = pk2(pv.z, pv.z), p3 = pk2(pv.w, pv.w);
            ffma2(acc2[h][0], p0, xv0.x); ffma2(acc2[h][1], p0, xv0.y);
            ffma2(acc2[h][0], p1, xv1.x); ffma2(acc2[h][1], p1, xv1.y);
            ffma2(acc2[h][0], p2, xv2.x); ffma2(acc2[h][1], p2, xv2.y);
            ffma2(acc2[h][0], p3, xv3.x); ffma2(acc2[h][1], p3, xv3.y);
        }
    }

    // half 1 stages into uS (wk no longer needed); half 0 merges and writes
    __syncthreads();
    if (half == 1) {
        #pragma unroll
        for (int h = 0; h < HH; h++) {
            float2 l0 = up2(acc2[h][0]), l1 = up2(acc2[h][1]);
            *(float4*)(uS + h * CC + 4 * u) = make_float4(l0.x, l0.y, l1.x, l1.y);
        }
    }
    __syncthreads();
    if (half == 0) {
        float* yp = g_ypart + ((size_t)(b * NCHUNK + ch)) * (HH * CC);
        #pragma unroll
        for (int h = 0; h < HH; h++) {
            float2 l0 = up2(acc2[h][0]), l1 = up2(acc2[h][1]);
            float4 sv = *(const float4*)(uS + h * CC + 4 * u);
            *(float4*)(yp + h * CC + 4 * u) =
                make_float4(l0.x + sv.x, l0.y + sv.y, l1.x + sv.z, l1.y + sv.w);
        }
    }
}

// ================= combine + ctx (exact round-7 version, measured fast) =================
__global__ __launch_bounds__(256) void k_combctx(const float* __restrict__ Wv,
                                                 const float* __restrict__ bv) {
    int b = blockIdx.x, h = blockIdx.y, t = threadIdx.x;
    __shared__ float ys[CC];
    __shared__ float red[4][DD];
    __shared__ float invZ_s;

    if (t < 32) {
        float z = 0.f;
        for (int c2 = t; c2 < NCHUNK; c2 += 32) z += g_z[(b * NCHUNK + c2) * HH + h];
        #pragma unroll
        for (int o = 16; o; o >>= 1) z += __shfl_xor_sync(~0u, z, o);
        if (t == 0) invZ_s = 1.f / z;
    }
    __syncthreads();
    float invZ = invZ_s;

    #pragma unroll
    for (int i = 0; i < 3; i++) {
        int c = t + 256 * i;
        const float* base = g_ypart + (size_t)b * NCHUNK * HH * CC + h * CC + c;
        float a0 = 0.f, a1 = 0.f, a2 = 0.f, a3 = 0.f;
        #pragma unroll 4
        for (int chn = 0; chn < NCHUNK - 3; chn += 4) {
            a0 += base[(size_t)chn * HH * CC];
            a1 += base[(size_t)(chn + 1) * HH * CC];
            a2 += base[(size_t)(chn + 2) * HH * CC];
            a3 += base[(size_t)(chn + 3) * HH * CC];
        }
        for (int chn = NCHUNK & ~3; chn < NCHUNK; chn++)
            a0 += base[(size_t)chn * HH * CC];
        ys[c] = ((a0 + a1) + (a2 + a3)) * invZ;
    }
    __syncthreads();

    int d = t & 63, part = t >> 6;
    const float* wp = Wv + h * DD + d;
    float a0 = 0.f, a1 = 0.f;
    #pragma unroll 8
    for (int c = part; c < CC; c += 8) {
        a0 = fmaf(ys[c],     wp[(size_t)c * CC],       a0);
        a1 = fmaf(ys[c + 4], wp[(size_t)(c + 4) * CC], a1);
    }
    red[part][d] = a0 + a1;
    __syncthreads();
    if (t < DD)
        g_ctx[b * CC + h * DD + t] =
            red[0][t] + red[1][t] + red[2][t] + red[3][t] + bv[h * DD + t];
}

// ================= out (exact round-7 version) =================
__global__ __launch_bounds__(192) void k_out(const float* __restrict__ Wo,
                                             const float* __restrict__ bo,
                                             float* __restrict__ out) {
    int b = blockIdx.x, part = blockIdx.y, t = threadIdx.x;
    __shared__ float cs[CC];
    for (int i = t; i < CC; i += 192) cs[i] = g_ctx[b * CC + i];
    __syncthreads();
    int cp = part * 192 + t;
    const float* wp = Wo + cp;
    float a0 = 0.f, a1 = 0.f, a2 = 0.f, a3 = 0.f;
    #pragma unroll 8
    for (int o = 0; o < CC; o += 4) {
        a0 = fmaf(cs[o],     wp[(size_t)o * CC],       a0);
        a1 = fmaf(cs[o + 1], wp[(size_t)(o + 1) * CC], a1);
        a2 = fmaf(cs[o + 2], wp[(size_t)(o + 2) * CC], a2);
        a3 = fmaf(cs[o + 3], wp[(size_t)(o + 3) * CC], a3);
    }
    out[(size_t)b * CC + cp] = (a0 + a1) + (a2 + a3) + bo[cp];
}

extern "C" void kernel_launch(void* const* d_in, const int* in_sizes, int n_in,
                              void* d_out, int out_size) {
    const float* x     = (const float*)d_in[0];
    const float* probe = (const float*)d_in[1];
    const float* Wq    = (const float*)d_in[2];
    const float* bq    = (const float*)d_in[3];
    const float* Wk    = (const float*)d_in[4];
    const float* bk    = (const float*)d_in[5];
    const float* Wv    = (const float*)d_in[6];
    const float* bv    = (const float*)d_in[7];
    const float* Wo    = (const float*)d_in[8];
    const float* bo    = (const float*)d_in[9];
    float* out = (float*)d_out;

    k_prep_qh<<<HH, 256>>>(probe, Wq, bq);          // #1
    k_prep_wk<<<HH, 256>>>(Wk);                     // #2
    k_prep_sb<<<1, 384>>>(bk);                      // #3
    k_fused<<<dim3(NCHUNK, BB), 384>>>(x);          // #4  <- profiled
    k_combctx<<<dim3(BB, HH), 256>>>(Wv, bv);       // #5
    k_out<<<dim3(BB, 4), 192>>>(Wo, bo, out);       // #6
}

// round 11
// speedup vs baseline: 1.4196x; 1.0227x over previous
#include <cuda_runtime.h>

#define BB 32
#define SS 4096
#define CC 768
#define HH 12
#define DD 64
#define NCHUNK 43
#define SCHUNK 96

// ---- scratch (device globals; allocation is forbidden) ----
__device__ float g_qhp[4 * HH * DD];                          // qh partials (4 c-slices)
__device__ float g_wk[HH * CC];                               // folded key weights
__device__ float g_sbias[HH];                                 // qh . bk
__device__ float g_z[BB * NCHUNK * HH];                       // per-chunk expsum
__device__ float g_ypart[(size_t)BB * NCHUNK * HH * CC];      // per-chunk partial y
__device__ float g_ctx[BB * CC];                              // context (h,d flattened)

typedef unsigned long long u64;

__device__ __forceinline__ u64 pk2(float a, float b) {
    u64 r; asm("mov.b64 %0,{%1,%2};" : "=l"(r) : "f"(a), "f"(b)); return r;
}
__device__ __forceinline__ float2 up2(u64 v) {
    float2 r; asm("mov.b64 {%0,%1},%2;" : "=f"(r.x), "=f"(r.y) : "l"(v)); return r;
}
__device__ __forceinline__ void ffma2(u64& d, u64 a, u64 b) {
    asm("fma.rn.f32x2 %0,%1,%2,%0;" : "+l"(d) : "l"(a), "l"(b));
}
__device__ __forceinline__ u64 vadd2(u64 a, u64 b) {
    u64 r; asm("add.rn.f32x2 %0,%1,%2;" : "=l"(r) : "l"(a), "l"(b)); return r;
}

// ================= prep 1: qh partials over 4 c-slices (48 blocks) =================
__global__ __launch_bounds__(256) void k_prep_qh(const float* __restrict__ probe,
                                                 const float* __restrict__ Wq) {
    int h = blockIdx.x, cs = blockIdx.y, t = threadIdx.x;
    __shared__ float red[4][DD];
    int d = t & 63, part = t >> 6;
    int c0 = cs * 192;
    float a = 0.f;
    #pragma unroll 8
    for (int c = c0 + part; c < c0 + 192; c += 4)
        a = fmaf(probe[c], Wq[(size_t)c * CC + h * DD + d], a);
    red[part][d] = a;
    __syncthreads();
    if (t < DD)
        g_qhp[cs * HH * DD + h * DD + t] = red[0][t] + red[1][t] + red[2][t] + red[3][t];
}

// ================= prep 2: wk[h,c] = sum_d Wk[c,h,d]*qh[h,d] (96 blocks) =================
__global__ __launch_bounds__(256) void k_prep_wk(const float* __restrict__ Wk,
                                                 const float* __restrict__ bq) {
    int h = blockIdx.x, sl = blockIdx.y, t = threadIdx.x;
    __shared__ float qs[DD];
    if (t < DD) {
        int i = h * DD + t;
        qs[t] = (g_qhp[i] + g_qhp[HH * DD + i] + g_qhp[2 * HH * DD + i]
               + g_qhp[3 * HH * DD + i] + bq[i]) * 0.125f;
    }
    __syncthreads();
    int base = sl * 96;
    for (int c = base + t; c < base + 96; c += 256) {
        const float4* wr = (const float4*)(Wk + (size_t)c * CC + h * DD);
        float s = 0.f;
        #pragma unroll
        for (int j = 0; j < DD / 4; j++) {
            float4 wv = wr[j];
            const float4 qv = *(const float4*)(qs + 4 * j);
            s += wv.x * qv.x + wv.y * qv.y + wv.z * qv.z + wv.w * qv.w;
        }
        g_wk[h * CC + c] = s;
    }
}

// ================= prep 3: sbias[h] = qh[h,:].bk[h,:] =================
__global__ __launch_bounds__(384) void k_prep_sb(const float* __restrict__ bq,
                                                 const float* __restrict__ bk) {
    int t = threadIdx.x, h = t >> 5, lane = t & 31;
    int i1 = h * DD + lane, i2 = i1 + 32;
    float q1 = (g_qhp[i1] + g_qhp[HH * DD + i1] + g_qhp[2 * HH * DD + i1]
              + g_qhp[3 * HH * DD + i1] + bq[i1]) * 0.125f;
    float q2 = (g_qhp[i2] + g_qhp[HH * DD + i2] + g_qhp[2 * HH * DD + i2]
              + g_qhp[3 * HH * DD + i2] + bq[i2]) * 0.125f;
    float a = q1 * bk[i1] + q2 * bk[i2];
    #pragma unroll
    for (int o = 16; o; o >>= 1) a += __shfl_xor_sync(~0u, a, o);
    if (lane == 0) g_sbias[h] = a;
}

// ================= fused: scores -> exp -> weighted accumulate (launch #4) ===========
// (FROZEN: identical to round-8/10 version, measured 254 us)
__global__ __launch_bounds__(384, 2) void k_fused(const float* __restrict__ x) {
    __shared__ __align__(16) float uS[HH * CC];      // wk (phase 1) / y stage (phase 2)
    __shared__ __align__(16) float sc[HH][SCHUNK];   // exp(score), plain f32, 4.5 KB
    __shared__ float zsh[HH];
    __shared__ float sbs[HH];

    int t = threadIdx.x, ch = blockIdx.x, b = blockIdx.y;
    int s0 = ch * SCHUNK;
    for (int i = t; i < HH * CC; i += 384) uS[i] = g_wk[i];
    if (t < HH) { sbs[t] = g_sbias[t]; zsh[t] = 0.f; }
    __syncthreads();

    int lane = t & 31, w = t >> 5, g = lane >> 3, q = lane & 7;
    const float* xb = x + (size_t)b * SS * CC;

    // ---- phase 1 ----
    {
        int p = w >> 1, h0 = (w & 1) * 6;
        int lbase = p * 16 + g;                        // local row = lbase + 4k
        const ulonglong2* xr[4];
        #pragma unroll
        for (int k = 0; k < 4; k++) {
            int row = s0 + lbase + 4 * k;
            int rc = row < SS ? row : SS - 1;
            xr[k] = (const ulonglong2*)(xb + (size_t)rc * CC) + q;
        }
        const ulonglong2* wq = (const ulonglong2*)uS + h0 * (CC / 4) + q;

        u64 acc[6][4];
        #pragma unroll
        for (int i = 0; i < 6; i++)
            #pragma unroll
            for (int k = 0; k < 4; k++) acc[i][k] = 0ull;

        #pragma unroll 4
        for (int j = 0; j < 24; j++) {
            ulonglong2 xv0 = xr[0][j * 8];
            ulonglong2 xv1 = xr[1][j * 8];
            ulonglong2 xv2 = xr[2][j * 8];
            ulonglong2 xv3 = xr[3][j * 8];
            #pragma unroll
            for (int i = 0; i < 6; i++) {
                ulonglong2 wv = wq[i * (CC / 4) + j * 8];
                ffma2(acc[i][0], xv0.x, wv.x); ffma2(acc[i][0], xv0.y, wv.y);
                ffma2(acc[i][1], xv1.x, wv.x); ffma2(acc[i][1], xv1.y, wv.y);
                ffma2(acc[i][2], xv2.x, wv.x); ffma2(acc[i][2], xv2.y, wv.y);
                ffma2(acc[i][3], xv3.x, wv.x); ffma2(acc[i][3], xv3.y, wv.y);
            }
        }
        #pragma unroll
        for (int i = 0; i < 6; i++) {
            float zt = 0.f;
            #pragma unroll
            for (int k = 0; k < 4; k++) {
                u64 v = acc[i][k];
                v = vadd2(v, __shfl_xor_sync(0xffffffffu, v, 4));
                v = vadd2(v, __shfl_xor_sync(0xffffffffu, v, 2));
                v = vadd2(v, __shfl_xor_sync(0xffffffffu, v, 1));
                if (q == 0) {
                    int lr = lbase + 4 * k;
                    float2 f = up2(v);
                    float e = (s0 + lr < SS) ? __expf(f.x + f.y + sbs[h0 + i]) : 0.f;
                    sc[h0 + i][lr] = e;
                    zt += e;
                }
            }
            float zq = (q == 0) ? zt : 0.f;
            zq += __shfl_xor_sync(0xffffffffu, zq, 8);
            zq += __shfl_xor_sync(0xffffffffu, zq, 16);
            if (lane == 0) atomicAdd(&zsh[h0 + i], zq);
        }
    }
    __syncthreads();
    if (t < HH) g_z[(b * NCHUNK + ch) * HH + t] = zsh[t];

    // ---- phase 2: y_part = sum_s p[h][s] * x[s,:] ----
    int half = t / 192, u = t - half * 192;            // cols 4u..4u+3
    int bs = half * 48;
    int rem = SS - (s0 + bs);
    int slim = rem < 0 ? 0 : (rem > 48 ? 48 : rem);    // multiple of 16
    const float* xp = xb + (size_t)(s0 + bs) * CC + 4 * u;

    u64 acc2[HH][2];
    #pragma unroll
    for (int h = 0; h < HH; h++) { acc2[h][0] = 0ull; acc2[h][1] = 0ull; }

    for (int s4 = 0; s4 < slim / 4; s4++) {
        ulonglong2 xv0 = *(const ulonglong2*)(xp + (size_t)(4 * s4)     * CC);
        ulonglong2 xv1 = *(const ulonglong2*)(xp + (size_t)(4 * s4 + 1) * CC);
        ulonglong2 xv2 = *(const ulonglong2*)(xp + (size_t)(4 * s4 + 2) * CC);
        ulonglong2 xv3 = *(const ulonglong2*)(xp + (size_t)(4 * s4 + 3) * CC);
        #pragma unroll
        for (int h = 0; h < HH; h++) {
            float4 pv = *(const float4*)&sc[h][bs + 4 * s4];
            u64 p0 = pk2(pv.x, pv.x), p1 = pk2(pv.y, pv.y);
            u64 p2 = pk2(pv.z, pv.z), p3 = pk2(pv.w, pv.w);
            ffma2(acc2[h][0], p0, xv0.x); ffma2(acc2[h][1], p0, xv0.y);
            ffma2(acc2[h][0], p1, xv1.x); ffma2(acc2[h][1], p1, xv1.y);
            ffma2(acc2[h][0], p2, xv2.x); ffma2(acc2[h][1], p2, xv2.y);
            ffma2(acc2[h][0], p3, xv3.x); ffma2(acc2[h][1], p3, xv3.y);
        }
    }

    // half 1 stages into uS (wk no longer needed); half 0 merges and writes
    __syncthreads();
    if (half == 1) {
        #pragma unroll
        for (int h = 0; h < HH; h++) {
            float2 l0 = up2(acc2[h][0]), l1 = up2(acc2[h][1]);
            *(float4*)(uS + h * CC + 4 * u) = make_float4(l0.x, l0.y, l1.x, l1.y);
        }
    }
    __syncthreads();
    if (half == 0) {
        float* yp = g_ypart + ((size_t)(b * NCHUNK + ch)) * (HH * CC);
        #pragma unroll
        for (int h = 0; h < HH; h++) {
            float2 l0 = up2(acc2[h][0]), l1 = up2(acc2[h][1]);
            float4 sv = *(const float4*)(uS + h * CC + 4 * u);
            *(float4*)(yp + h * CC + 4 * u) =
                make_float4(l0.x + sv.x, l0.y + sv.y, l1.x + sv.z, l1.y + sv.w);
        }
    }
}

// ================= combine + ctx (FROZEN round-7 version) =================
__global__ __launch_bounds__(256) void k_combctx(const float* __restrict__ Wv,
                                                 const float* __restrict__ bv) {
    int b = blockIdx.x, h = blockIdx.y, t = threadIdx.x;
    __shared__ float ys[CC];
    __shared__ float red[4][DD];
    __shared__ float invZ_s;

    if (t < 32) {
        float z = 0.f;
        for (int c2 = t; c2 < NCHUNK; c2 += 32) z += g_z[(b * NCHUNK + c2) * HH + h];
        #pragma unroll
        for (int o = 16; o; o >>= 1) z += __shfl_xor_sync(~0u, z, o);
        if (t == 0) invZ_s = 1.f / z;
    }
    __syncthreads();
    float invZ = invZ_s;

    #pragma unroll
    for (int i = 0; i < 3; i++) {
        int c = t + 256 * i;
        const float* base = g_ypart + (size_t)b * NCHUNK * HH * CC + h * CC + c;
        float a0 = 0.f, a1 = 0.f, a2 = 0.f, a3 = 0.f;
        #pragma unroll 4
        for (int chn = 0; chn < NCHUNK - 3; chn += 4) {
            a0 += base[(size_t)chn * HH * CC];
            a1 += base[(size_t)(chn + 1) * HH * CC];
            a2 += base[(size_t)(chn + 2) * HH * CC];
            a3 += base[(size_t)(chn + 3) * HH * CC];
        }
        for (int chn = NCHUNK & ~3; chn < NCHUNK; chn++)
            a0 += base[(size_t)chn * HH * CC];
        ys[c] = ((a0 + a1) + (a2 + a3)) * invZ;
    }
    __syncthreads();

    int d = t & 63, part = t >> 6;
    const float* wp = Wv + h * DD + d;
    float a0 = 0.f, a1 = 0.f;
    #pragma unroll 8
    for (int c = part; c < CC; c += 8) {
        a0 = fmaf(ys[c],     wp[(size_t)c * CC],       a0);
        a1 = fmaf(ys[c + 4], wp[(size_t)(c + 4) * CC], a1);
    }
    red[part][d] = a0 + a1;
    __syncthreads();
    if (t < DD)
        g_ctx[b * CC + h * DD + t] =
            red[0][t] + red[1][t] + red[2][t] + red[3][t] + bv[h * DD + t];
}

// ================= out (FROZEN round-7 version) =================
__global__ __launch_bounds__(192) void k_out(const float* __restrict__ Wo,
                                             const float* __restrict__ bo,
                                             float* __restrict__ out) {
    int b = blockIdx.x, part = blockIdx.y, t = threadIdx.x;
    __shared__ float cs[CC];
    for (int i = t; i < CC; i += 192) cs[i] = g_ctx[b * CC + i];
    __syncthreads();
    int cp = part * 192 + t;
    const float* wp = Wo + cp;
    float a0 = 0.f, a1 = 0.f, a2 = 0.f, a3 = 0.f;
    #pragma unroll 8
    for (int o = 0; o < CC; o += 4) {
        a0 = fmaf(cs[o],     wp[(size_t)o * CC],       a0);
        a1 = fmaf(cs[o + 1], wp[(size_t)(o + 1) * CC], a1);
        a2 = fmaf(cs[o + 2], wp[(size_t)(o + 2) * CC], a2);
        a3 = fmaf(cs[o + 3], wp[(size_t)(o + 3) * CC], a3);
    }
    out[(size_t)b * CC + cp] = (a0 + a1) + (a2 + a3) + bo[cp];
}

extern "C" void kernel_launch(void* const* d_in, const int* in_sizes, int n_in,
                              void* d_out, int out_size) {
    const float* x     = (const float*)d_in[0];
    const float* probe = (const float*)d_in[1];
    const float* Wq    = (const float*)d_in[2];
    const float* bq    = (const float*)d_in[3];
    const float* Wk    = (const float*)d_in[4];
    const float* bk    = (const float*)d_in[5];
    const float* Wv    = (const float*)d_in[6];
    const float* bv    = (const float*)d_in[7];
    const float* Wo    = (const float*)d_in[8];
    const float* bo    = (const float*)d_in[9];
    float* out = (float*)d_out;

    k_prep_qh<<<dim3(HH, 4), 256>>>(probe, Wq);     // #1  (48 blocks)
    k_prep_wk<<<dim3(HH, 8), 256>>>(Wk, bq);        // #2  (96 blocks)
    k_prep_sb<<<1, 384>>>(bq, bk);                  // #3
    k_fused<<<dim3(NCHUNK, BB), 384>>>(x);          // #4  <- profiled slot
    k_combctx<<<dim3(BB, HH), 256>>>(Wv, bv);       // #5
    k_out<<<dim3(BB, 4), 192>>>(Wo, bo, out);       // #6
}

// round 13
// speedup vs baseline: 1.6735x; 1.1788x over previous
#include <cuda_runtime.h>
#include <cuda_bf16.h>
#include <cstdint>

#define BB 32
#define SS 4096
#define CC 768
#define HH 12
#define DD 64
#define NCHUNK 32
#define SCHUNK 128

// ---- scratch (device globals; allocation is forbidden) ----
__device__ float g_qhp[4 * HH * DD];                          // qh partials (4 c-slices)
__device__ __nv_bfloat16 g_wkh[HH * CC];                      // folded key weights, bf16 hi
__device__ __nv_bfloat16 g_wkl[HH * CC];                      // folded key weights, bf16 lo
__device__ float g_sbias[HH];                                 // qh . bk
__device__ float g_z[BB * NCHUNK * HH];                       // per-chunk expsum
__device__ float g_ypart[(size_t)BB * NCHUNK * HH * CC];      // per-chunk partial y
__device__ float g_ctx[BB * CC];                              // context (h,d flattened)

// ================= warp-mma helpers (sm_80 PTX; compiles on plain sm_103) ==========
__device__ __forceinline__ uint32_t smem_u32(const void* p) {
    uint32_t a;
    asm("{ .reg .u64 t; cvta.to.shared.u64 t, %1; cvt.u32.u64 %0, t; }" : "=r"(a) : "l"(p));
    return a;
}
__device__ __forceinline__ void ldm_x4(uint32_t* r, uint32_t addr) {
    asm volatile("ldmatrix.sync.aligned.m8n8.x4.shared.b16 {%0,%1,%2,%3}, [%4];"
        : "=r"(r[0]), "=r"(r[1]), "=r"(r[2]), "=r"(r[3]) : "r"(addr));
}
__device__ __forceinline__ void ldm_x2(uint32_t* r, uint32_t addr) {
    asm volatile("ldmatrix.sync.aligned.m8n8.x2.shared.b16 {%0,%1}, [%2];"
        : "=r"(r[0]), "=r"(r[1]) : "r"(addr));
}
__device__ __forceinline__ void ldm_x2t(uint32_t* r, uint32_t addr) {
    asm volatile("ldmatrix.sync.aligned.m8n8.x2.trans.shared.b16 {%0,%1}, [%2];"
        : "=r"(r[0]), "=r"(r[1]) : "r"(addr));
}
__device__ __forceinline__ void mma16816(float* d, const uint32_t* a, const uint32_t* b) {
    asm volatile("mma.sync.aligned.m16n8k16.row.col.f32.bf16.bf16.f32 "
        "{%0,%1,%2,%3}, {%4,%5,%6,%7}, {%8,%9}, {%0,%1,%2,%3};"
        : "+f"(d[0]), "+f"(d[1]), "+f"(d[2]), "+f"(d[3])
        : "r"(a[0]), "r"(a[1]), "r"(a[2]), "r"(a[3]), "r"(b[0]), "r"(b[1]));
}
__device__ __forceinline__ uint32_t pbf2(float a, float b) {
    __nv_bfloat162 h = __floats2bfloat162_rn(a, b);
    return *reinterpret_cast<uint32_t*>(&h);
}

// ---- smem layout (bytes). Padded strides keep every ldmatrix 8-lane group
// on distinct 16B banks: 528 = 33*16, 1552 = 97*16, 272 = 17*16.
#define OFF_XH   0u
#define OFF_XL   67584u
#define OFF_WKH  135168u
#define OFF_WKL  160000u
#define OFF_PH   184832u
#define OFF_PL   189184u
#define OFF_SBS  193536u
#define OFF_ZSH  193600u
#define SMEM_TOTAL 193664

// ================= prep 1: qh partials over 4 c-slices =================
__global__ __launch_bounds__(256) void k_prep_qh(const float* __restrict__ probe,
                                                 const float* __restrict__ Wq) {
    int h = blockIdx.x, cs = blockIdx.y, t = threadIdx.x;
    __shared__ float red[4][DD];
    int d = t & 63, part = t >> 6;
    int c0 = cs * 192;
    float a = 0.f;
    #pragma unroll 8
    for (int c = c0 + part; c < c0 + 192; c += 4)
        a = fmaf(probe[c], Wq[(size_t)c * CC + h * DD + d], a);
    red[part][d] = a;
    __syncthreads();
    if (t < DD)
        g_qhp[cs * HH * DD + h * DD + t] = red[0][t] + red[1][t] + red[2][t] + red[3][t];
}

// ================= prep 2: wk = fold(Wk,qh) -> bf16 hi/lo =================
__global__ __launch_bounds__(256) void k_prep_wk(const float* __restrict__ Wk,
                                                 const float* __restrict__ bq) {
    int h = blockIdx.x, sl = blockIdx.y, t = threadIdx.x;
    __shared__ float qs[DD];
    if (t < DD) {
        int i = h * DD + t;
        qs[t] = (g_qhp[i] + g_qhp[HH * DD + i] + g_qhp[2 * HH * DD + i]
               + g_qhp[3 * HH * DD + i] + bq[i]) * 0.125f;
    }
    __syncthreads();
    int base = sl * 96;
    for (int c = base + t; c < base + 96; c += 256) {
        const float4* wr = (const float4*)(Wk + (size_t)c * CC + h * DD);
        float s = 0.f;
        #pragma unroll
        for (int j = 0; j < DD / 4; j++) {
            float4 wv = wr[j];
            const float4 qv = *(const float4*)(qs + 4 * j);
            s += wv.x * qv.x + wv.y * qv.y + wv.z * qv.z + wv.w * qv.w;
        }
        __nv_bfloat16 hb = __float2bfloat16(s);
        g_wkh[h * CC + c] = hb;
        g_wkl[h * CC + c] = __float2bfloat16(s - __bfloat162float(hb));
    }
}

// ================= prep 3: sbias[h] = qh[h,:].bk[h,:] =================
__global__ __launch_bounds__(384) void k_prep_sb(const float* __restrict__ bq,
                                                 const float* __restrict__ bk) {
    int t = threadIdx.x, h = t >> 5, lane = t & 31;
    int i1 = h * DD + lane, i2 = i1 + 32;
    float q1 = (g_qhp[i1] + g_qhp[HH * DD + i1] + g_qhp[2 * HH * DD + i1]
              + g_qhp[3 * HH * DD + i1] + bq[i1]) * 0.125f;
    float q2 = (g_qhp[i2] + g_qhp[HH * DD + i2] + g_qhp[2 * HH * DD + i2]
              + g_qhp[3 * HH * DD + i2] + bq[i2]) * 0.125f;
    float a = q1 * bk[i1] + q2 * bk[i2];
    #pragma unroll
    for (int o = 16; o; o >>= 1) a += __shfl_xor_sync(~0u, a, o);
    if (lane == 0) g_sbias[h] = a;
}

// ================= fused (mma.sync): scores MMA -> exp -> y MMA =================
// grid (32, 32), 384 threads (12 warps), 194 KB smem, 1 block/SM.
// Phase 1: S[128s,16h] = X . WK^T, warps 0-7 own 16-row m-tiles, bf16 hi/lo (3 mma).
// Phase 2: Y[16h,768c] = P . X, A=P in regs, B=X via ldmatrix.trans (same staging).
__global__ __launch_bounds__(384, 1) void k_fused(const float* __restrict__ x) {
    extern __shared__ __align__(16) char smem[];
    const uint32_t sb = smem_u32(smem);
    int t = threadIdx.x, w = t >> 5, lane = t & 31;
    int ch = blockIdx.x, b = blockIdx.y;
    int s0 = ch * SCHUNK;
    const float* xb = x + (size_t)b * SS * CC;
    int gid = lane >> 2, tig = lane & 3;

    if (t < 16) {
        ((float*)(smem + OFF_ZSH))[t] = 0.f;
        ((float*)(smem + OFF_SBS))[t] = (t < HH) ? g_sbias[t] : 0.f;
    }
    // stage wk hi/lo [16][768], stride 1552B, rows 12-15 zeroed
    for (int i = t; i < 16 * 192; i += 384) {
        int h = i / 192, c4 = i % 192;
        uint2 hv = make_uint2(0u, 0u), lv = make_uint2(0u, 0u);
        if (h < HH) {
            hv = *(const uint2*)(g_wkh + h * CC + c4 * 4);
            lv = *(const uint2*)(g_wkl + h * CC + c4 * 4);
        }
        *(uint2*)(smem + OFF_WKH + h * 1552 + c4 * 8) = hv;
        *(uint2*)(smem + OFF_WKL + h * 1552 + c4 * 8) = lv;
    }

    float d0[4] = {0.f, 0.f, 0.f, 0.f}, d1[4] = {0.f, 0.f, 0.f, 0.f};
    uint32_t xA   = sb + OFF_XH + (16 * (w & 7) + (lane & 15)) * 528 + (lane >> 4) * 16;
    uint32_t xAl  = xA + (OFF_XL - OFF_XH);
    uint32_t wkB  = sb + OFF_WKH + (lane & 7) * 1552 + ((lane >> 3) & 1) * 16;
    uint32_t wkBl = wkB + (OFF_WKL - OFF_WKH);

    // ===== phase 1: 3 k-slices of 256 c =====
    for (int sl = 0; sl < 3; sl++) {
        __syncthreads();
        const float* xs = xb + (size_t)s0 * CC + sl * 256;
        for (int i = t; i < 8192; i += 384) {
            int r = i >> 6, c4 = i & 63;
            float4 v = *(const float4*)(xs + (size_t)r * CC + c4 * 4);
            uint32_t h0 = pbf2(v.x, v.y), h1 = pbf2(v.z, v.w);
            float l0 = v.x - __uint_as_float(h0 << 16);
            float l1 = v.y - __uint_as_float(h0 & 0xffff0000u);
            float l2 = v.z - __uint_as_float(h1 << 16);
            float l3 = v.w - __uint_as_float(h1 & 0xffff0000u);
            *(uint2*)(smem + OFF_XH + r * 528 + c4 * 8) = make_uint2(h0, h1);
            *(uint2*)(smem + OFF_XL + r * 528 + c4 * 8) = make_uint2(pbf2(l0, l1), pbf2(l2, l3));
        }
        __syncthreads();
        if (w < 8) {
            #pragma unroll 4
            for (int kk = 0; kk < 16; kk++) {
                uint32_t ah[4], al[4], bh[2], bl[2];
                ldm_x4(ah, xA + kk * 32);
                ldm_x4(al, xAl + kk * 32);
                uint32_t co = sl * 512 + kk * 32;
                ldm_x2(bh, wkB + co);
                ldm_x2(bl, wkBl + co);
                mma16816(d0, ah, bh); mma16816(d0, ah, bl); mma16816(d0, al, bh);
                ldm_x2(bh, wkB + 8 * 1552 + co);
                ldm_x2(bl, wkBl + 8 * 1552 + co);
                mma16816(d1, ah, bh); mma16816(d1, ah, bl); mma16816(d1, al, bh);
            }
        }
    }

    // ===== exp + P (bf16 hi/lo, [16h][128s] stride 272B) + z =====
    if (w < 8) {
        const float* sbs = (const float*)(smem + OFF_SBS);
        int h0 = 2 * tig, r0 = 16 * w + gid;
        float e[8];
        e[0] = __expf(d0[0] + sbs[h0]);     e[1] = __expf(d0[1] + sbs[h0 + 1]);
        e[2] = __expf(d0[2] + sbs[h0]);     e[3] = __expf(d0[3] + sbs[h0 + 1]);
        e[4] = __expf(d1[0] + sbs[h0 + 8]); e[5] = __expf(d1[1] + sbs[h0 + 9]);
        e[6] = __expf(d1[2] + sbs[h0 + 8]); e[7] = __expf(d1[3] + sbs[h0 + 9]);
        #pragma unroll
        for (int k = 0; k < 8; k++) {
            int hh = (k < 4 ? h0 : h0 + 8) + (k & 1);
            int ss = r0 + ((k >> 1) & 1) * 8;
            __nv_bfloat16 hb = __float2bfloat16(e[k]);
            float lo = e[k] - __bfloat162float(hb);
            *(__nv_bfloat16*)(smem + OFF_PH + hh * 272 + ss * 2) = hb;
            *(__nv_bfloat16*)(smem + OFF_PL + hh * 272 + ss * 2) = __float2bfloat16(lo);
        }
        float v0 = e[0] + e[2], v1 = e[1] + e[3], v2 = e[4] + e[6], v3 = e[5] + e[7];
        #pragma unroll
        for (int o = 4; o < 32; o <<= 1) {
            v0 += __shfl_xor_sync(~0u, v0, o);
            v1 += __shfl_xor_sync(~0u, v1, o);
            v2 += __shfl_xor_sync(~0u, v2, o);
            v3 += __shfl_xor_sync(~0u, v3, o);
        }
        if (lane < 4) {
            float* zsh = (float*)(smem + OFF_ZSH);
            atomicAdd(&zsh[2 * lane],     v0);
            atomicAdd(&zsh[2 * lane + 1], v1);
            atomicAdd(&zsh[2 * lane + 8], v2);
            atomicAdd(&zsh[2 * lane + 9], v3);
        }
    }
    __syncthreads();
    if (t < HH) g_z[(b * NCHUNK + ch) * HH + t] = ((float*)(smem + OFF_ZSH))[t];

    // A' = P fragments, kept in registers (8 k-steps, hi+lo)
    uint32_t pA  = sb + OFF_PH + (lane & 15) * 272 + (lane >> 4) * 16;
    uint32_t pAl = pA + (OFF_PL - OFF_PH);
    uint32_t aph[8][4], apl[8][4];
    #pragma unroll
    for (int kk = 0; kk < 8; kk++) {
        ldm_x4(aph[kk], pA + kk * 32);
        ldm_x4(apl[kk], pAl + kk * 32);
    }

    // ===== phase 2: Y[16h][c] = P . X, 3 k... c-slices of 256 =====
    float* ypb = g_ypart + (size_t)(b * NCHUNK + ch) * (HH * CC);
    for (int sl = 0; sl < 3; sl++) {
        __syncthreads();
        const float* xs = xb + (size_t)s0 * CC + sl * 256;
        for (int i = t; i < 8192; i += 384) {
            int r = i >> 6, c4 = i & 63;
            float4 v = *(const float4*)(xs + (size_t)r * CC + c4 * 4);
            uint32_t h0 = pbf2(v.x, v.y), h1 = pbf2(v.z, v.w);
            float l0 = v.x - __uint_as_float(h0 << 16);
            float l1 = v.y - __uint_as_float(h0 & 0xffff0000u);
            float l2 = v.z - __uint_as_float(h1 << 16);
            float l3 = v.w - __uint_as_float(h1 & 0xffff0000u);
            *(uint2*)(smem + OFF_XH + r * 528 + c4 * 8) = make_uint2(h0, h1);
            *(uint2*)(smem + OFF_XL + r * 528 + c4 * 8) = make_uint2(pbf2(l0, l1), pbf2(l2, l3));
        }
        __syncthreads();
        for (int nt = w; nt < 32; nt += 12) {
            float d[4] = {0.f, 0.f, 0.f, 0.f};
            uint32_t xt = sb + OFF_XH + (lane & 15) * 528 + nt * 16;
            #pragma unroll
            for (int kk = 0; kk < 8; kk++) {
                uint32_t bh[2], bl[2];
                ldm_x2t(bh, xt + kk * 16 * 528);
                ldm_x2t(bl, xt + kk * 16 * 528 + (OFF_XL - OFF_XH));
                mma16816(d, aph[kk], bh);
                mma16816(d, aph[kk], bl);
                mma16816(d, apl[kk], bh);
            }
            int c = sl * 256 + 8 * nt + 2 * tig;
            *(float2*)(ypb + (size_t)gid * CC + c) = make_float2(d[0], d[1]);
            if (gid + 8 < HH)
                *(float2*)(ypb + (size_t)(gid + 8) * CC + c) = make_float2(d[2], d[3]);
        }
    }
}

// ================= combine + ctx (FROZEN round-7 version) =================
__global__ __launch_bounds__(256) void k_combctx(const float* __restrict__ Wv,
                                                 const float* __restrict__ bv) {
    int b = blockIdx.x, h = blockIdx.y, t = threadIdx.x;
    __shared__ float ys[CC];
    __shared__ float red[4][DD];
    __shared__ float invZ_s;

    if (t < 32) {
        float z = 0.f;
        for (int c2 = t; c2 < NCHUNK; c2 += 32) z += g_z[(b * NCHUNK + c2) * HH + h];
        #pragma unroll
        for (int o = 16; o; o >>= 1) z += __shfl_xor_sync(~0u, z, o);
        if (t == 0) invZ_s = 1.f / z;
    }
    __syncthreads();
    float invZ = invZ_s;

    #pragma unroll
    for (int i = 0; i < 3; i++) {
        int c = t + 256 * i;
        const float* base = g_ypart + (size_t)b * NCHUNK * HH * CC + h * CC + c;
        float a0 = 0.f, a1 = 0.f, a2 = 0.f, a3 = 0.f;
        #pragma unroll 4
        for (int chn = 0; chn < NCHUNK - 3; chn += 4) {
            a0 += base[(size_t)chn * HH * CC];
            a1 += base[(size_t)(chn + 1) * HH * CC];
            a2 += base[(size_t)(chn + 2) * HH * CC];
            a3 += base[(size_t)(chn + 3) * HH * CC];
        }
        for (int chn = NCHUNK & ~3; chn < NCHUNK; chn++)
            a0 += base[(size_t)chn * HH * CC];
        ys[c] = ((a0 + a1) + (a2 + a3)) * invZ;
    }
    __syncthreads();

    int d = t & 63, part = t >> 6;
    const float* wp = Wv + h * DD + d;
    float a0 = 0.f, a1 = 0.f;
    #pragma unroll 8
    for (int c = part; c < CC; c += 8) {
        a0 = fmaf(ys[c],     wp[(size_t)c * CC],       a0);
        a1 = fmaf(ys[c + 4], wp[(size_t)(c + 4) * CC], a1);
    }
    red[part][d] = a0 + a1;
    __syncthreads();
    if (t < DD)
        g_ctx[b * CC + h * DD + t] =
            red[0][t] + red[1][t] + red[2][t] + red[3][t] + bv[h * DD + t];
}

// ================= out (FROZEN round-7 version) =================
__global__ __launch_bounds__(192) void k_out(const float* __restrict__ Wo,
                                             const float* __restrict__ bo,
                                             float* __restrict__ out) {
    int b = blockIdx.x, part = blockIdx.y, t = threadIdx.x;
    __shared__ float cs[CC];
    for (int i = t; i < CC; i += 192) cs[i] = g_ctx[b * CC + i];
    __syncthreads();
    int cp = part * 192 + t;
    const float* wp = Wo + cp;
    float a0 = 0.f, a1 = 0.f, a2 = 0.f, a3 = 0.f;
    #pragma unroll 8
    for (int o = 0; o < CC; o += 4) {
        a0 = fmaf(cs[o],     wp[(size_t)o * CC],       a0);
        a1 = fmaf(cs[o + 1], wp[(size_t)(o + 1) * CC], a1);
        a2 = fmaf(cs[o + 2], wp[(size_t)(o + 2) * CC], a2);
        a3 = fmaf(cs[o + 3], wp[(size_t)(o + 3) * CC], a3);
    }
    out[(size_t)b * CC + cp] = (a0 + a1) + (a2 + a3) + bo[cp];
}

extern "C" void kernel_launch(void* const* d_in, const int* in_sizes, int n_in,
                              void* d_out, int out_size) {
    const float* x     = (const float*)d_in[0];
    const float* probe = (const float*)d_in[1];
    const float* Wq    = (const float*)d_in[2];
    const float* bq    = (const float*)d_in[3];
    const float* Wk    = (const float*)d_in[4];
    const float* bk    = (const float*)d_in[5];
    const float* Wv    = (const float*)d_in[6];
    const float* bv    = (const float*)d_in[7];
    const float* Wo    = (const float*)d_in[8];
    const float* bo    = (const float*)d_in[9];
    float* out = (float*)d_out;

    cudaFuncSetAttribute(k_fused, cudaFuncAttributeMaxDynamicSharedMemorySize, SMEM_TOTAL);

    k_prep_qh<<<dim3(HH, 4), 256>>>(probe, Wq);             // #1
    k_prep_wk<<<dim3(HH, 8), 256>>>(Wk, bq);                // #2
    k_prep_sb<<<1, 384>>>(bq, bk);                          // #3
    k_fused<<<dim3(NCHUNK, BB), 384, SMEM_TOTAL>>>(x);      // #4  <- profiled slot
    k_combctx<<<dim3(BB, HH), 256>>>(Wv, bv);               // #5
    k_out<<<dim3(BB, 4), 192>>>(Wo, bo, out);               // #6
}

// round 14
// speedup vs baseline: 1.6853x; 1.0070x over previous
#include <cuda_runtime.h>
#include <cuda_bf16.h>
#include <cstdint>

#define BB 32
#define SS 4096
#define CC 768
#define HH 12
#define DD 64
#define NCHUNK 32
#define SCHUNK 128

// ---- scratch (device globals; allocation is forbidden) ----
__device__ float g_qhp[4 * HH * DD];                          // qh partials (4 c-slices)
__device__ __nv_bfloat16 g_wkh[16 * CC];                      // folded key weights, bf16 hi (16 rows, 12-15 zero)
__device__ __nv_bfloat16 g_wkl[16 * CC];                      // folded key weights, bf16 lo
__device__ float g_sbias[HH];                                 // qh . bk
__device__ float g_z[BB * NCHUNK * HH];                       // per-chunk expsum
__device__ float g_ypart[(size_t)BB * NCHUNK * HH * CC];      // per-chunk partial y
__device__ float g_ctx[BB * CC];                              // context (h,d flattened)

// ================= warp-mma helpers (sm_80 PTX; compiles on plain sm_103) ==========
__device__ __forceinline__ uint32_t smem_u32(const void* p) {
    uint32_t a;
    asm("{ .reg .u64 t; cvta.to.shared.u64 t, %1; cvt.u32.u64 %0, t; }" : "=r"(a) : "l"(p));
    return a;
}
__device__ __forceinline__ void ldm_x4(uint32_t* r, uint32_t addr) {
    asm volatile("ldmatrix.sync.aligned.m8n8.x4.shared.b16 {%0,%1,%2,%3}, [%4];"
        : "=r"(r[0]), "=r"(r[1]), "=r"(r[2]), "=r"(r[3]) : "r"(addr));
}
__device__ __forceinline__ void ldm_x2(uint32_t* r, uint32_t addr) {
    asm volatile("ldmatrix.sync.aligned.m8n8.x2.shared.b16 {%0,%1}, [%2];"
        : "=r"(r[0]), "=r"(r[1]) : "r"(addr));
}
__device__ __forceinline__ void ldm_x2t(uint32_t* r, uint32_t addr) {
    asm volatile("ldmatrix.sync.aligned.m8n8.x2.trans.shared.b16 {%0,%1}, [%2];"
        : "=r"(r[0]), "=r"(r[1]) : "r"(addr));
}
__device__ __forceinline__ void mma16816(float* d, const uint32_t* a, const uint32_t* b) {
    asm volatile("mma.sync.aligned.m16n8k16.row.col.f32.bf16.bf16.f32 "
        "{%0,%1,%2,%3}, {%4,%5,%6,%7}, {%8,%9}, {%0,%1,%2,%3};"
        : "+f"(d[0]), "+f"(d[1]), "+f"(d[2]), "+f"(d[3])
        : "r"(a[0]), "r"(a[1]), "r"(a[2]), "r"(a[3]), "r"(b[0]), "r"(b[1]));
}
__device__ __forceinline__ uint32_t pbf2(float a, float b) {
    __nv_bfloat162 h = __floats2bfloat162_rn(a, b);
    return *reinterpret_cast<uint32_t*>(&h);
}

// ---- smem layout (bytes). Row stride 272 = 17*16: consecutive rows land on
// distinct bank groups (272/4 mod 32 = 4), conflict-free for ldmatrix.
#define OFF_XH   0u
#define OFF_XL   34816u
#define OFF_WKH  69632u
#define OFF_WKL  73984u
#define OFF_PH   78336u
#define OFF_PL   82688u
#define OFF_SBS  87040u
#define OFF_ZSH  87104u
#define SMEM_TOTAL 87168

// ================= prep 1: qh partials over 4 c-slices =================
__global__ __launch_bounds__(256) void k_prep_qh(const float* __restrict__ probe,
                                                 const float* __restrict__ Wq) {
    int h = blockIdx.x, cs = blockIdx.y, t = threadIdx.x;
    __shared__ float red[4][DD];
    int d = t & 63, part = t >> 6;
    int c0 = cs * 192;
    float a = 0.f;
    #pragma unroll 8
    for (int c = c0 + part; c < c0 + 192; c += 4)
        a = fmaf(probe[c], Wq[(size_t)c * CC + h * DD + d], a);
    red[part][d] = a;
    __syncthreads();
    if (t < DD)
        g_qhp[cs * HH * DD + h * DD + t] = red[0][t] + red[1][t] + red[2][t] + red[3][t];
}

// ================= prep 2: wk = fold(Wk,qh) -> bf16 hi/lo (rows 12-15 zeroed) ==========
__global__ __launch_bounds__(256) void k_prep_wk(const float* __restrict__ Wk,
                                                 const float* __restrict__ bq) {
    int h = blockIdx.x, sl = blockIdx.y, t = threadIdx.x;
    __shared__ float qs[DD];
    if (t < DD) {
        int i = h * DD + t;
        qs[t] = (g_qhp[i] + g_qhp[HH * DD + i] + g_qhp[2 * HH * DD + i]
               + g_qhp[3 * HH * DD + i] + bq[i]) * 0.125f;
    }
    __syncthreads();
    int base = sl * 96;
    for (int c = base + t; c < base + 96; c += 256) {
        const float4* wr = (const float4*)(Wk + (size_t)c * CC + h * DD);
        float s = 0.f;
        #pragma unroll
        for (int j = 0; j < DD / 4; j++) {
            float4 wv = wr[j];
            const float4 qv = *(const float4*)(qs + 4 * j);
            s += wv.x * qv.x + wv.y * qv.y + wv.z * qv.z + wv.w * qv.w;
        }
        __nv_bfloat16 hb = __float2bfloat16(s);
        g_wkh[h * CC + c] = hb;
        g_wkl[h * CC + c] = __float2bfloat16(s - __bfloat162float(hb));
        if (h < 4) {   // zero pad rows 12..15
            g_wkh[(HH + h) * CC + c] = __float2bfloat16(0.f);
            g_wkl[(HH + h) * CC + c] = __float2bfloat16(0.f);
        }
    }
}

// ================= prep 3: sbias[h] = qh[h,:].bk[h,:] =================
__global__ __launch_bounds__(384) void k_prep_sb(const float* __restrict__ bq,
                                                 const float* __restrict__ bk) {
    int t = threadIdx.x, h = t >> 5, lane = t & 31;
    int i1 = h * DD + lane, i2 = i1 + 32;
    float q1 = (g_qhp[i1] + g_qhp[HH * DD + i1] + g_qhp[2 * HH * DD + i1]
              + g_qhp[3 * HH * DD + i1] + bq[i1]) * 0.125f;
    float q2 = (g_qhp[i2] + g_qhp[HH * DD + i2] + g_qhp[2 * HH * DD + i2]
              + g_qhp[3 * HH * DD + i2] + bq[i2]) * 0.125f;
    float a = q1 * bk[i1] + q2 * bk[i2];
    #pragma unroll
    for (int o = 16; o; o >>= 1) a += __shfl_xor_sync(~0u, a, o);
    if (lane == 0) g_sbias[h] = a;
}

// ================= fused (mma.sync): scores MMA -> exp -> y MMA =================
// grid (32, 32), 384 threads (12 warps), 87 KB smem, 2 blocks/SM (24 warps).
// 6 slices of 128 cols; wk staged per slice; phase-2 P fragments reloaded in
// two k-halves to stay under the 84-reg budget for 2 blocks/SM.
__global__ __launch_bounds__(384, 2) void k_fused(const float* __restrict__ x) {
    extern __shared__ __align__(16) char smem[];
    const uint32_t sb = smem_u32(smem);
    int t = threadIdx.x, w = t >> 5, lane = t & 31;
    int ch = blockIdx.x, b = blockIdx.y;
    int s0 = ch * SCHUNK;
    const float* xb = x + (size_t)b * SS * CC;
    int gid = lane >> 2, tig = lane & 3;

    if (t < 16) {
        ((float*)(smem + OFF_ZSH))[t] = 0.f;
        ((float*)(smem + OFF_SBS))[t] = (t < HH) ? g_sbias[t] : 0.f;
    }

    float d0[4] = {0.f, 0.f, 0.f, 0.f}, d1[4] = {0.f, 0.f, 0.f, 0.f};
    uint32_t xA   = sb + OFF_XH + (16 * (w & 7) + (lane & 15)) * 272 + (lane >> 4) * 16;
    uint32_t xAl  = xA + (OFF_XL - OFF_XH);
    uint32_t wkB  = sb + OFF_WKH + (lane & 7) * 272 + ((lane >> 3) & 1) * 16;
    uint32_t wkBl = wkB + (OFF_WKL - OFF_WKH);

    // ===== phase 1: scores over 6 c-slices of 128 =====
    for (int sl = 0; sl < 6; sl++) {
        __syncthreads();
        const float* xs = xb + (size_t)s0 * CC + sl * 128;
        for (int i = t; i < 4096; i += 384) {
            int r = i >> 5, c4 = i & 31;
            float4 v = *(const float4*)(xs + (size_t)r * CC + c4 * 4);
            uint32_t h0 = pbf2(v.x, v.y), h1 = pbf2(v.z, v.w);
            float l0 = v.x - __uint_as_float(h0 << 16);
            float l1 = v.y - __uint_as_float(h0 & 0xffff0000u);
            float l2 = v.z - __uint_as_float(h1 << 16);
            float l3 = v.w - __uint_as_float(h1 & 0xffff0000u);
            *(uint2*)(smem + OFF_XH + r * 272 + c4 * 8) = make_uint2(h0, h1);
            *(uint2*)(smem + OFF_XL + r * 272 + c4 * 8) = make_uint2(pbf2(l0, l1), pbf2(l2, l3));
        }
        for (int i = t; i < 512; i += 384) {
            int h = i >> 5, c4 = i & 31;
            *(uint2*)(smem + OFF_WKH + h * 272 + c4 * 8) =
                *(const uint2*)(g_wkh + h * CC + sl * 128 + c4 * 4);
            *(uint2*)(smem + OFF_WKL + h * 272 + c4 * 8) =
                *(const uint2*)(g_wkl + h * CC + sl * 128 + c4 * 4);
        }
        __syncthreads();
        if (w < 8) {
            #pragma unroll 4
            for (int kk = 0; kk < 8; kk++) {
                uint32_t ah[4], al[4], bh[2], bl[2];
                ldm_x4(ah, xA + kk * 32);
                ldm_x4(al, xAl + kk * 32);
                ldm_x2(bh, wkB + kk * 32);
                ldm_x2(bl, wkBl + kk * 32);
                mma16816(d0, ah, bh); mma16816(d0, ah, bl); mma16816(d0, al, bh);
                ldm_x2(bh, wkB + 8 * 272 + kk * 32);
                ldm_x2(bl, wkBl + 8 * 272 + kk * 32);
                mma16816(d1, ah, bh); mma16816(d1, ah, bl); mma16816(d1, al, bh);
            }
        }
    }

    // ===== exp + P (bf16 hi/lo, [16h][128s] stride 272B) + z =====
    if (w < 8) {
        const float* sbs = (const float*)(smem + OFF_SBS);
        int h0 = 2 * tig, r0 = 16 * w + gid;
        float e[8];
        e[0] = __expf(d0[0] + sbs[h0]);     e[1] = __expf(d0[1] + sbs[h0 + 1]);
        e[2] = __expf(d0[2] + sbs[h0]);     e[3] = __expf(d0[3] + sbs[h0 + 1]);
        e[4] = __expf(d1[0] + sbs[h0 + 8]); e[5] = __expf(d1[1] + sbs[h0 + 9]);
        e[6] = __expf(d1[2] + sbs[h0 + 8]); e[7] = __expf(d1[3] + sbs[h0 + 9]);
        #pragma unroll
        for (int k = 0; k < 8; k++) {
            int hh = (k < 4 ? h0 : h0 + 8) + (k & 1);
            int ss = r0 + ((k >> 1) & 1) * 8;
            __nv_bfloat16 hb = __float2bfloat16(e[k]);
            float lo = e[k] - __bfloat162float(hb);
            *(__nv_bfloat16*)(smem + OFF_PH + hh * 272 + ss * 2) = hb;
            *(__nv_bfloat16*)(smem + OFF_PL + hh * 272 + ss * 2) = __float2bfloat16(lo);
        }
        float v0 = e[0] + e[2], v1 = e[1] + e[3], v2 = e[4] + e[6], v3 = e[5] + e[7];
        #pragma unroll
        for (int o = 4; o < 32; o <<= 1) {
            v0 += __shfl_xor_sync(~0u, v0, o);
            v1 += __shfl_xor_sync(~0u, v1, o);
            v2 += __shfl_xor_sync(~0u, v2, o);
            v3 += __shfl_xor_sync(~0u, v3, o);
        }
        if (lane < 4) {
            float* zsh = (float*)(smem + OFF_ZSH);
            atomicAdd(&zsh[2 * lane],     v0);
            atomicAdd(&zsh[2 * lane + 1], v1);
            atomicAdd(&zsh[2 * lane + 8], v2);
            atomicAdd(&zsh[2 * lane + 9], v3);
        }
    }
    __syncthreads();
    if (t < HH) g_z[(b * NCHUNK + ch) * HH + t] = ((float*)(smem + OFF_ZSH))[t];

    // ===== phase 2: Y[16h][c] = P . X per 128-col slice, k split in halves =====
    uint32_t pA  = sb + OFF_PH + (lane & 15) * 272 + (lane >> 4) * 16;
    uint32_t pAl = pA + (OFF_PL - OFF_PH);
    float* ypb = g_ypart + (size_t)(b * NCHUNK + ch) * (HH * CC);

    for (int sl = 0; sl < 6; sl++) {
        __syncthreads();
        const float* xs = xb + (size_t)s0 * CC + sl * 128;
        for (int i = t; i < 4096; i += 384) {
            int r = i >> 5, c4 = i & 31;
            float4 v = *(const float4*)(xs + (size_t)r * CC + c4 * 4);
            uint32_t h0 = pbf2(v.x, v.y), h1 = pbf2(v.z, v.w);
            float l0 = v.x - __uint_as_float(h0 << 16);
            float l1 = v.y - __uint_as_float(h0 & 0xffff0000u);
            float l2 = v.z - __uint_as_float(h1 << 16);
            float l3 = v.w - __uint_as_float(h1 & 0xffff0000u);
            *(uint2*)(smem + OFF_XH + r * 272 + c4 * 8) = make_uint2(h0, h1);
            *(uint2*)(smem + OFF_XL + r * 272 + c4 * 8) = make_uint2(pbf2(l0, l1), pbf2(l2, l3));
        }
        __syncthreads();

        // nt tiles (16 per slice): warp w owns nt = w and w+12 (if < 16)
        float dA[4] = {0.f, 0.f, 0.f, 0.f}, dB[4] = {0.f, 0.f, 0.f, 0.f};
        int ntA = w, ntB = w + 12;
        uint32_t xtA = sb + OFF_XH + (lane & 15) * 272 + ntA * 16;
        uint32_t xtB = sb + OFF_XH + (lane & 15) * 272 + ntB * 16;

        #pragma unroll
        for (int kh = 0; kh < 2; kh++) {
            uint32_t aph[4][4], apl[4][4];
            #pragma unroll
            for (int j = 0; j < 4; j++) {
                ldm_x4(aph[j], pA + (kh * 4 + j) * 32);
                ldm_x4(apl[j], pAl + (kh * 4 + j) * 32);
            }
            #pragma unroll
            for (int j = 0; j < 4; j++) {
                uint32_t ko = (uint32_t)((kh * 4 + j) * 16 * 272);
                uint32_t bh[2], bl[2];
                ldm_x2t(bh, xtA + ko);
                ldm_x2t(bl, xtA + ko + (OFF_XL - OFF_XH));
                mma16816(dA, aph[j], bh);
                mma16816(dA, aph[j], bl);
                mma16816(dA, apl[j], bh);
                if (ntB < 16) {
                    ldm_x2t(bh, xtB + ko);
                    ldm_x2t(bl, xtB + ko + (OFF_XL - OFF_XH));
                    mma16816(dB, aph[j], bh);
                    mma16816(dB, aph[j], bl);
                    mma16816(dB, apl[j], bh);
                }
            }
        }
        int cA = sl * 128 + 8 * ntA + 2 * tig;
        *(float2*)(ypb + (size_t)gid * CC + cA) = make_float2(dA[0], dA[1]);
        if (gid + 8 < HH)
            *(float2*)(ypb + (size_t)(gid + 8) * CC + cA) = make_float2(dA[2], dA[3]);
        if (ntB < 16) {
            int cB = sl * 128 + 8 * ntB + 2 * tig;
            *(float2*)(ypb + (size_t)gid * CC + cB) = make_float2(dB[0], dB[1]);
            if (gid + 8 < HH)
                *(float2*)(ypb + (size_t)(gid + 8) * CC + cB) = make_float2(dB[2], dB[3]);
        }
    }
}

// ================= combine + ctx (FROZEN round-7 version) =================
__global__ __launch_bounds__(256) void k_combctx(const float* __restrict__ Wv,
                                                 const float* __restrict__ bv) {
    int b = blockIdx.x, h = blockIdx.y, t = threadIdx.x;
    __shared__ float ys[CC];
    __shared__ float red[4][DD];
    __shared__ float invZ_s;

    if (t < 32) {
        float z = 0.f;
        for (int c2 = t; c2 < NCHUNK; c2 += 32) z += g_z[(b * NCHUNK + c2) * HH + h];
        #pragma unroll
        for (int o = 16; o; o >>= 1) z += __shfl_xor_sync(~0u, z, o);
        if (t == 0) invZ_s = 1.f / z;
    }
    __syncthreads();
    float invZ = invZ_s;

    #pragma unroll
    for (int i = 0; i < 3; i++) {
        int c = t + 256 * i;
        const float* base = g_ypart + (size_t)b * NCHUNK * HH * CC + h * CC + c;
        float a0 = 0.f, a1 = 0.f, a2 = 0.f, a3 = 0.f;
        #pragma unroll 4
        for (int chn = 0; chn < NCHUNK - 3; chn += 4) {
            a0 += base[(size_t)chn * HH * CC];
            a1 += base[(size_t)(chn + 1) * HH * CC];
            a2 += base[(size_t)(chn + 2) * HH * CC];
            a3 += base[(size_t)(chn + 3) * HH * CC];
        }
        for (int chn = NCHUNK & ~3; chn < NCHUNK; chn++)
            a0 += base[(size_t)chn * HH * CC];
        ys[c] = ((a0 + a1) + (a2 + a3)) * invZ;
    }
    __syncthreads();

    int d = t & 63, part = t >> 6;
    const float* wp = Wv + h * DD + d;
    float a0 = 0.f, a1 = 0.f;
    #pragma unroll 8
    for (int c = part; c < CC; c += 8) {
        a0 = fmaf(ys[c],     wp[(size_t)c * CC],       a0);
        a1 = fmaf(ys[c + 4], wp[(size_t)(c + 4) * CC], a1);
    }
    red[part][d] = a0 + a1;
    __syncthreads();
    if (t < DD)
        g_ctx[b * CC + h * DD + t] =
            red[0][t] + red[1][t] + red[2][t] + red[3][t] + bv[h * DD + t];
}

// ================= out (FROZEN round-7 version) =================
__global__ __launch_bounds__(192) void k_out(const float* __restrict__ Wo,
                                             const float* __restrict__ bo,
                                             float* __restrict__ out) {
    int b = blockIdx.x, part = blockIdx.y, t = threadIdx.x;
    __shared__ float cs[CC];
    for (int i = t; i < CC; i += 192) cs[i] = g_ctx[b * CC + i];
    __syncthreads();
    int cp = part * 192 + t;
    const float* wp = Wo + cp;
    float a0 = 0.f, a1 = 0.f, a2 = 0.f, a3 = 0.f;
    #pragma unroll 8
    for (int o = 0; o < CC; o += 4) {
        a0 = fmaf(cs[o],     wp[(size_t)o * CC],       a0);
        a1 = fmaf(cs[o + 1], wp[(size_t)(o + 1) * CC], a1);
        a2 = fmaf(cs[o + 2], wp[(size_t)(o + 2) * CC], a2);
        a3 = fmaf(cs[o + 3], wp[(size_t)(o + 3) * CC], a3);
    }
    out[(size_t)b * CC + cp] = (a0 + a1) + (a2 + a3) + bo[cp];
}

extern "C" void kernel_launch(void* const* d_in, const int* in_sizes, int n_in,
                              void* d_out, int out_size) {
    const float* x     = (const float*)d_in[0];
    const float* probe = (const float*)d_in[1];
    const float* Wq    = (const float*)d_in[2];
    const float* bq    = (const float*)d_in[3];
    const float* Wk    = (const float*)d_in[4];
    const float* bk    = (const float*)d_in[5];
    const float* Wv    = (const float*)d_in[6];
    const float* bv    = (const float*)d_in[7];
    const float* Wo    = (const float*)d_in[8];
    const float* bo    = (const float*)d_in[9];
    float* out = (float*)d_out;

    cudaFuncSetAttribute(k_fused, cudaFuncAttributeMaxDynamicSharedMemorySize, SMEM_TOTAL);

    k_prep_qh<<<dim3(HH, 4), 256>>>(probe, Wq);             // #1
    k_prep_wk<<<dim3(HH, 8), 256>>>(Wk, bq);                // #2
    k_prep_sb<<<1, 384>>>(bq, bk);                          // #3
    k_fused<<<dim3(NCHUNK, BB), 384, SMEM_TOTAL>>>(x);      // #4  <- profiled slot
    k_combctx<<<dim3(BB, HH), 256>>>(Wv, bv);               // #5
    k_out<<<dim3(BB, 4), 192>>>(Wo, bo, out);               // #6
}

// round 15
// speedup vs baseline: 2.0423x; 1.2119x over previous
#include <cuda_runtime.h>
#include <cuda_bf16.h>
#include <cstdint>

#define BB 32
#define SS 4096
#define CC 768
#define HH 12
#define DD 64
#define NCHUNK 32
#define SCHUNK 128

// ---- scratch (device globals; allocation is forbidden) ----
__device__ float g_qhp[4 * HH * DD];                          // qh partials (4 c-slices)
__device__ __nv_bfloat16 g_wkh[16 * CC];                      // folded key weights, bf16 hi (rows 12-15 zero)
__device__ __nv_bfloat16 g_wkl[16 * CC];                      // folded key weights, bf16 lo
__device__ float g_sbias[HH];                                 // qh . bk
__device__ float g_z[BB * NCHUNK * HH];                       // per-chunk expsum
__device__ float g_ypart[(size_t)BB * NCHUNK * HH * CC];      // per-chunk partial y
__device__ float g_ctx[BB * CC];                              // context (h,d flattened)

// ================= warp-mma helpers (sm_80 PTX; compiles on plain sm_103) ==========
__device__ __forceinline__ uint32_t smem_u32(const void* p) {
    uint32_t a;
    asm("{ .reg .u64 t; cvta.to.shared.u64 t, %1; cvt.u32.u64 %0, t; }" : "=r"(a) : "l"(p));
    return a;
}
__device__ __forceinline__ void ldm_x4(uint32_t* r, uint32_t addr) {
    asm volatile("ldmatrix.sync.aligned.m8n8.x4.shared.b16 {%0,%1,%2,%3}, [%4];"
        : "=r"(r[0]), "=r"(r[1]), "=r"(r[2]), "=r"(r[3]) : "r"(addr));
}
__device__ __forceinline__ void ldm_x2(uint32_t* r, uint32_t addr) {
    asm volatile("ldmatrix.sync.aligned.m8n8.x2.shared.b16 {%0,%1}, [%2];"
        : "=r"(r[0]), "=r"(r[1]) : "r"(addr));
}
__device__ __forceinline__ void ldm_x2t(uint32_t* r, uint32_t addr) {
    asm volatile("ldmatrix.sync.aligned.m8n8.x2.trans.shared.b16 {%0,%1}, [%2];"
        : "=r"(r[0]), "=r"(r[1]) : "r"(addr));
}
__device__ __forceinline__ void mma16816(float* d, const uint32_t* a, const uint32_t* b) {
    asm volatile("mma.sync.aligned.m16n8k16.row.col.f32.bf16.bf16.f32 "
        "{%0,%1,%2,%3}, {%4,%5,%6,%7}, {%8,%9}, {%0,%1,%2,%3};"
        : "+f"(d[0]), "+f"(d[1]), "+f"(d[2]), "+f"(d[3])
        : "r"(a[0]), "r"(a[1]), "r"(a[2]), "r"(a[3]), "r"(b[0]), "r"(b[1]));
}
__device__ __forceinline__ uint32_t pbf2(float a, float b) {
    __nv_bfloat162 h = __floats2bfloat162_rn(a, b);
    return *reinterpret_cast<uint32_t*>(&h);
}

// ---- smem layout (bytes). Row stride 272 = 17*16 (conflict-free ldmatrix).
#define OFF_XH   0u
#define OFF_XL   34816u
#define OFF_WKH  69632u
#define OFF_WKL  73984u
#define OFF_PH   78336u
#define OFF_PL   82688u
#define OFF_SBS  87040u
#define OFF_ZSH  87104u
#define SMEM_TOTAL 87168

// ================= prep 1: qh partials over 4 c-slices =================
__global__ __launch_bounds__(256) void k_prep_qh(const float* __restrict__ probe,
                                                 const float* __restrict__ Wq) {
    int h = blockIdx.x, cs = blockIdx.y, t = threadIdx.x;
    __shared__ float red[4][DD];
    int d = t & 63, part = t >> 6;
    int c0 = cs * 192;
    float a = 0.f;
    #pragma unroll 8
    for (int c = c0 + part; c < c0 + 192; c += 4)
        a = fmaf(probe[c], Wq[(size_t)c * CC + h * DD + d], a);
    red[part][d] = a;
    __syncthreads();
    if (t < DD)
        g_qhp[cs * HH * DD + h * DD + t] = red[0][t] + red[1][t] + red[2][t] + red[3][t];
}

// ================= prep 2: wk = fold(Wk,qh) -> bf16 hi/lo (rows 12-15 zeroed) ==========
__global__ __launch_bounds__(256) void k_prep_wk(const float* __restrict__ Wk,
                                                 const float* __restrict__ bq) {
    int h = blockIdx.x, sl = blockIdx.y, t = threadIdx.x;
    __shared__ float qs[DD];
    if (t < DD) {
        int i = h * DD + t;
        qs[t] = (g_qhp[i] + g_qhp[HH * DD + i] + g_qhp[2 * HH * DD + i]
               + g_qhp[3 * HH * DD + i] + bq[i]) * 0.125f;
    }
    __syncthreads();
    int base = sl * 96;
    for (int c = base + t; c < base + 96; c += 256) {
        const float4* wr = (const float4*)(Wk + (size_t)c * CC + h * DD);
        float s = 0.f;
        #pragma unroll
        for (int j = 0; j < DD / 4; j++) {
            float4 wv = wr[j];
            const float4 qv = *(const float4*)(qs + 4 * j);
            s += wv.x * qv.x + wv.y * qv.y + wv.z * qv.z + wv.w * qv.w;
        }
        __nv_bfloat16 hb = __float2bfloat16(s);
        g_wkh[h * CC + c] = hb;
        g_wkl[h * CC + c] = __float2bfloat16(s - __bfloat162float(hb));
        if (h < 4) {   // zero pad rows 12..15
            g_wkh[(HH + h) * CC + c] = __float2bfloat16(0.f);
            g_wkl[(HH + h) * CC + c] = __float2bfloat16(0.f);
        }
    }
}

// ================= prep 3: sbias[h] = qh[h,:].bk[h,:] =================
__global__ __launch_bounds__(384) void k_prep_sb(const float* __restrict__ bq,
                                                 const float* __restrict__ bk) {
    int t = threadIdx.x, h = t >> 5, lane = t & 31;
    int i1 = h * DD + lane, i2 = i1 + 32;
    float q1 = (g_qhp[i1] + g_qhp[HH * DD + i1] + g_qhp[2 * HH * DD + i1]
              + g_qhp[3 * HH * DD + i1] + bq[i1]) * 0.125f;
    float q2 = (g_qhp[i2] + g_qhp[HH * DD + i2] + g_qhp[2 * HH * DD + i2]
              + g_qhp[3 * HH * DD + i2] + bq[i2]) * 0.125f;
    float a = q1 * bk[i1] + q2 * bk[i2];
    #pragma unroll
    for (int o = 16; o; o >>= 1) a += __shfl_xor_sync(~0u, a, o);
    if (lane == 0) g_sbias[h] = a;
}

// ================= fused (mma.sync): scores MMA -> exp -> y MMA =================
// grid (32, 32), 512 threads (16 warps), 87 KB smem, 2 blocks/SM (32 warps).
// Staging is exactly 8 iters/thread (full unroll, MLP 8). Phase 1: warps 0-7
// heads 0-7, warps 8-15 heads 8-15 (one acc set each). Phase 2: one n-tile
// per warp, slices in REVERSE order for L2 recency.
__global__ __launch_bounds__(512, 2) void k_fused(const float* __restrict__ x) {
    extern __shared__ __align__(16) char smem[];
    const uint32_t sb = smem_u32(smem);
    int t = threadIdx.x, w = t >> 5, lane = t & 31;
    int ch = blockIdx.x, b = blockIdx.y;
    int s0 = ch * SCHUNK;
    const float* xb = x + (size_t)b * SS * CC;
    int gid = lane >> 2, tig = lane & 3;

    if (t < 16) {
        ((float*)(smem + OFF_ZSH))[t] = 0.f;
        ((float*)(smem + OFF_SBS))[t] = (t < HH) ? g_sbias[t] : 0.f;
    }

    int mt = w & 7, hb = (w >> 3) * 8;
    float d0[4] = {0.f, 0.f, 0.f, 0.f};
    uint32_t xA   = sb + OFF_XH + (16 * mt + (lane & 15)) * 272 + (lane >> 4) * 16;
    uint32_t xAl  = xA + (OFF_XL - OFF_XH);
    uint32_t wkB  = sb + OFF_WKH + ((lane & 7) + hb) * 272 + ((lane >> 3) & 1) * 16;
    uint32_t wkBl = wkB + (OFF_WKL - OFF_WKH);

    // ===== phase 1: scores over 6 c-slices of 128 =====
    for (int sl = 0; sl < 6; sl++) {
        __syncthreads();
        const float* xs = xb + (size_t)s0 * CC + sl * 128;
        #pragma unroll
        for (int j = 0; j < 8; j++) {
            int i = t + j * 512;
            int r = i >> 5, c4 = i & 31;
            float4 v = *(const float4*)(xs + (size_t)r * CC + c4 * 4);
            uint32_t h0 = pbf2(v.x, v.y), h1 = pbf2(v.z, v.w);
            float l0 = v.x - __uint_as_float(h0 << 16);
            float l1 = v.y - __uint_as_float(h0 & 0xffff0000u);
            float l2 = v.z - __uint_as_float(h1 << 16);
            float l3 = v.w - __uint_as_float(h1 & 0xffff0000u);
            *(uint2*)(smem + OFF_XH + r * 272 + c4 * 8) = make_uint2(h0, h1);
            *(uint2*)(smem + OFF_XL + r * 272 + c4 * 8) = make_uint2(pbf2(l0, l1), pbf2(l2, l3));
        }
        {   // wk slice: exactly 1 item/thread
            int h = t >> 5, c4 = t & 31;
            *(uint2*)(smem + OFF_WKH + h * 272 + c4 * 8) =
                *(const uint2*)(g_wkh + h * CC + sl * 128 + c4 * 4);
            *(uint2*)(smem + OFF_WKL + h * 272 + c4 * 8) =
                *(const uint2*)(g_wkl + h * CC + sl * 128 + c4 * 4);
        }
        __syncthreads();
        #pragma unroll 4
        for (int kk = 0; kk < 8; kk++) {
            uint32_t ah[4], al[4], bh[2], bl[2];
            ldm_x4(ah, xA + kk * 32);
            ldm_x4(al, xAl + kk * 32);
            ldm_x2(bh, wkB + kk * 32);
            ldm_x2(bl, wkBl + kk * 32);
            mma16816(d0, ah, bh);
            mma16816(d0, ah, bl);
            mma16816(d0, al, bh);
        }
    }

    // ===== exp + P (bf16 hi/lo, [16h][128s] stride 272B) + z =====
    {
        const float* sbs = (const float*)(smem + OFF_SBS);
        int h0 = hb + 2 * tig, r0 = 16 * mt + gid;
        float e[4];
        e[0] = __expf(d0[0] + sbs[h0]);
        e[1] = __expf(d0[1] + sbs[h0 + 1]);
        e[2] = __expf(d0[2] + sbs[h0]);
        e[3] = __expf(d0[3] + sbs[h0 + 1]);
        #pragma unroll
        for (int k = 0; k < 4; k++) {
            int hh = h0 + (k & 1);
            int ss = r0 + (k >> 1) * 8;
            __nv_bfloat16 hbf = __float2bfloat16(e[k]);
            float lo = e[k] - __bfloat162float(hbf);
            *(__nv_bfloat16*)(smem + OFF_PH + hh * 272 + ss * 2) = hbf;
            *(__nv_bfloat16*)(smem + OFF_PL + hh * 272 + ss * 2) = __float2bfloat16(lo);
        }
        float v0 = e[0] + e[2], v1 = e[1] + e[3];
        #pragma unroll
        for (int o = 4; o < 32; o <<= 1) {
            v0 += __shfl_xor_sync(~0u, v0, o);
            v1 += __shfl_xor_sync(~0u, v1, o);
        }
        if (lane < 4) {
            float* zsh = (float*)(smem + OFF_ZSH);
            atomicAdd(&zsh[hb + 2 * lane],     v0);
            atomicAdd(&zsh[hb + 2 * lane + 1], v1);
        }
    }
    __syncthreads();
    if (t < HH) g_z[(b * NCHUNK + ch) * HH + t] = ((float*)(smem + OFF_ZSH))[t];

    // ===== phase 2: Y[16h][c] = P . X, one n-tile per warp, REVERSE slices =====
    uint32_t pA  = sb + OFF_PH + (lane & 15) * 272 + (lane >> 4) * 16;
    uint32_t pAl = pA + (OFF_PL - OFF_PH);
    float* ypb = g_ypart + (size_t)(b * NCHUNK + ch) * (HH * CC);

    for (int sl = 5; sl >= 0; sl--) {
        __syncthreads();
        const float* xs = xb + (size_t)s0 * CC + sl * 128;
        #pragma unroll
        for (int j = 0; j < 8; j++) {
            int i = t + j * 512;
            int r = i >> 5, c4 = i & 31;
            float4 v = *(const float4*)(xs + (size_t)r * CC + c4 * 4);
            uint32_t h0 = pbf2(v.x, v.y), h1 = pbf2(v.z, v.w);
            float l0 = v.x - __uint_as_float(h0 << 16);
            float l1 = v.y - __uint_as_float(h0 & 0xffff0000u);
            float l2 = v.z - __uint_as_float(h1 << 16);
            float l3 = v.w - __uint_as_float(h1 & 0xffff0000u);
            *(uint2*)(smem + OFF_XH + r * 272 + c4 * 8) = make_uint2(h0, h1);
            *(uint2*)(smem + OFF_XL + r * 272 + c4 * 8) = make_uint2(pbf2(l0, l1), pbf2(l2, l3));
        }
        __syncthreads();

        float d[4] = {0.f, 0.f, 0.f, 0.f};
        uint32_t xt = sb + OFF_XH + (lane & 15) * 272 + w * 16;

        #pragma unroll
        for (int kh = 0; kh < 2; kh++) {
            uint32_t aph[4][4], apl[4][4];
            #pragma unroll
            for (int j = 0; j < 4; j++) {
                ldm_x4(aph[j], pA + (kh * 4 + j) * 32);
                ldm_x4(apl[j], pAl + (kh * 4 + j) * 32);
            }
            #pragma unroll
            for (int j = 0; j < 4; j++) {
                uint32_t ko = (uint32_t)((kh * 4 + j) * 16 * 272);
                uint32_t bh[2], bl[2];
                ldm_x2t(bh, xt + ko);
                ldm_x2t(bl, xt + ko + (OFF_XL - OFF_XH));
                mma16816(d, aph[j], bh);
                mma16816(d, aph[j], bl);
                mma16816(d, apl[j], bh);
            }
        }
        int c = sl * 128 + 8 * w + 2 * tig;
        *(float2*)(ypb + (size_t)gid * CC + c) = make_float2(d[0], d[1]);
        if (gid + 8 < HH)
            *(float2*)(ypb + (size_t)(gid + 8) * CC + c) = make_float2(d[2], d[3]);
    }
}

// ================= combine + ctx (FROZEN round-7 version) =================
__global__ __launch_bounds__(256) void k_combctx(const float* __restrict__ Wv,
                                                 const float* __restrict__ bv) {
    int b = blockIdx.x, h = blockIdx.y, t = threadIdx.x;
    __shared__ float ys[CC];
    __shared__ float red[4][DD];
    __shared__ float invZ_s;

    if (t < 32) {
        float z = 0.f;
        for (int c2 = t; c2 < NCHUNK; c2 += 32) z += g_z[(b * NCHUNK + c2) * HH + h];
        #pragma unroll
        for (int o = 16; o; o >>= 1) z += __shfl_xor_sync(~0u, z, o);
        if (t == 0) invZ_s = 1.f / z;
    }
    __syncthreads();
    float invZ = invZ_s;

    #pragma unroll
    for (int i = 0; i < 3; i++) {
        int c = t + 256 * i;
        const float* base = g_ypart + (size_t)b * NCHUNK * HH * CC + h * CC + c;
        float a0 = 0.f, a1 = 0.f, a2 = 0.f, a3 = 0.f;
        #pragma unroll 4
        for (int chn = 0; chn < NCHUNK - 3; chn += 4) {
            a0 += base[(size_t)chn * HH * CC];
            a1 += base[(size_t)(chn + 1) * HH * CC];
            a2 += base[(size_t)(chn + 2) * HH * CC];
            a3 += base[(size_t)(chn + 3) * HH * CC];
        }
        for (int chn = NCHUNK & ~3; chn < NCHUNK; chn++)
            a0 += base[(size_t)chn * HH * CC];
        ys[c] = ((a0 + a1) + (a2 + a3)) * invZ;
    }
    __syncthreads();

    int d = t & 63, part = t >> 6;
    const float* wp = Wv + h * DD + d;
    float a0 = 0.f, a1 = 0.f;
    #pragma unroll 8
    for (int c = part; c < CC; c += 8) {
        a0 = fmaf(ys[c],     wp[(size_t)c * CC],       a0);
        a1 = fmaf(ys[c + 4], wp[(size_t)(c + 4) * CC], a1);
    }
    red[part][d] = a0 + a1;
    __syncthreads();
    if (t < DD)
        g_ctx[b * CC + h * DD + t] =
            red[0][t] + red[1][t] + red[2][t] + red[3][t] + bv[h * DD + t];
}

// ================= out (FROZEN round-7 version) =================
__global__ __launch_bounds__(192) void k_out(const float* __restrict__ Wo,
                                             const float* __restrict__ bo,
                                             float* __restrict__ out) {
    int b = blockIdx.x, part = blockIdx.y, t = threadIdx.x;
    __shared__ float cs[CC];
    for (int i = t; i < CC; i += 192) cs[i] = g_ctx[b * CC + i];
    __syncthreads();
    int cp = part * 192 + t;
    const float* wp = Wo + cp;
    float a0 = 0.f, a1 = 0.f, a2 = 0.f, a3 = 0.f;
    #pragma unroll 8
    for (int o = 0; o < CC; o += 4) {
        a0 = fmaf(cs[o],     wp[(size_t)o * CC],       a0);
        a1 = fmaf(cs[o + 1], wp[(size_t)(o + 1) * CC], a1);
        a2 = fmaf(cs[o + 2], wp[(size_t)(o + 2) * CC], a2);
        a3 = fmaf(cs[o + 3], wp[(size_t)(o + 3) * CC], a3);
    }
    out[(size_t)b * CC + cp] = (a0 + a1) + (a2 + a3) + bo[cp];
}

extern "C" void kernel_launch(void* const* d_in, const int* in_sizes, int n_in,
                              void* d_out, int out_size) {
    const float* x     = (const float*)d_in[0];
    const float* probe = (const float*)d_in[1];
    const float* Wq    = (const float*)d_in[2];
    const float* bq    = (const float*)d_in[3];
    const float* Wk    = (const float*)d_in[4];
    const float* bk    = (const float*)d_in[5];
    const float* Wv    = (const float*)d_in[6];
    const float* bv    = (const float*)d_in[7];
    const float* Wo    = (const float*)d_in[8];
    const float* bo    = (const float*)d_in[9];
    float* out = (float*)d_out;

    cudaFuncSetAttribute(k_fused, cudaFuncAttributeMaxDynamicSharedMemorySize, SMEM_TOTAL);

    k_prep_qh<<<dim3(HH, 4), 256>>>(probe, Wq);             // #1
    k_prep_wk<<<dim3(HH, 8), 256>>>(Wk, bq);                // #2
    k_prep_sb<<<1, 384>>>(bq, bk);                          // #3
    k_fused<<<dim3(NCHUNK, BB), 512, SMEM_TOTAL>>>(x);      // #4  <- profiled slot
    k_combctx<<<dim3(BB, HH), 256>>>(Wv, bv);               // #5
    k_out<<<dim3(BB, 4), 192>>>(Wo, bo, out);               // #6
}

// round 16
// speedup vs baseline: 2.1197x; 1.0379x over previous
#include <cuda_runtime.h>
#include <cuda_bf16.h>
#include <cstdint>

#define BB 32
#define SS 4096
#define CC 768
#define HH 12
#define DD 64
#define NCHUNK 32
#define SCHUNK 128

// ---- scratch (device globals; allocation is forbidden) ----
__device__ float g_qhp[4 * HH * DD];                          // qh partials (4 c-slices)
__device__ __nv_bfloat16 g_wkh[16 * CC];                      // folded key weights, bf16 hi (rows 12-15 zero)
__device__ __nv_bfloat16 g_wkl[16 * CC];                      // folded key weights, bf16 lo
__device__ float g_sbias[HH];                                 // qh . bk
__device__ float g_z[BB * NCHUNK * HH];                       // per-chunk expsum
__device__ float g_ypart[(size_t)BB * NCHUNK * HH * CC];      // per-chunk partial y
__device__ float g_ctx[BB * CC];                              // context (h,d flattened)

// ================= warp-mma helpers (sm_80 PTX; compiles on plain sm_103) ==========
__device__ __forceinline__ uint32_t smem_u32(const void* p) {
    uint32_t a;
    asm("{ .reg .u64 t; cvta.to.shared.u64 t, %1; cvt.u32.u64 %0, t; }" : "=r"(a) : "l"(p));
    return a;
}
__device__ __forceinline__ void ldm_x4(uint32_t* r, uint32_t addr) {
    asm volatile("ldmatrix.sync.aligned.m8n8.x4.shared.b16 {%0,%1,%2,%3}, [%4];"
        : "=r"(r[0]), "=r"(r[1]), "=r"(r[2]), "=r"(r[3]) : "r"(addr));
}
__device__ __forceinline__ void ldm_x4t(uint32_t* r, uint32_t addr) {
    asm volatile("ldmatrix.sync.aligned.m8n8.x4.trans.shared.b16 {%0,%1,%2,%3}, [%4];"
        : "=r"(r[0]), "=r"(r[1]), "=r"(r[2]), "=r"(r[3]) : "r"(addr));
}
__device__ __forceinline__ void mma16816(float* d, const uint32_t* a, const uint32_t* b) {
    asm volatile("mma.sync.aligned.m16n8k16.row.col.f32.bf16.bf16.f32 "
        "{%0,%1,%2,%3}, {%4,%5,%6,%7}, {%8,%9}, {%0,%1,%2,%3};"
        : "+f"(d[0]), "+f"(d[1]), "+f"(d[2]), "+f"(d[3])
        : "r"(a[0]), "r"(a[1]), "r"(a[2]), "r"(a[3]), "r"(b[0]), "r"(b[1]));
}
__device__ __forceinline__ uint32_t pbf2(float a, float b) {
    __nv_bfloat162 h = __floats2bfloat162_rn(a, b);
    return *reinterpret_cast<uint32_t*>(&h);
}

// ---- smem layout (bytes). Row stride 272 = 17*16 (conflict-free ldmatrix).
#define OFF_XH   0u
#define OFF_XL   34816u
#define OFF_WKH  69632u
#define OFF_WKL  73984u
#define OFF_PH   78336u
#define OFF_PL   82688u
#define OFF_SBS  87040u
#define OFF_ZSH  87104u
#define SMEM_TOTAL 87168

// ================= prep 1: qh partials over 4 c-slices =================
__global__ __launch_bounds__(256) void k_prep_qh(const float* __restrict__ probe,
                                                 const float* __restrict__ Wq) {
    int h = blockIdx.x, cs = blockIdx.y, t = threadIdx.x;
    __shared__ float red[4][DD];
    int d = t & 63, part = t >> 6;
    int c0 = cs * 192;
    float a = 0.f;
    #pragma unroll 8
    for (int c = c0 + part; c < c0 + 192; c += 4)
        a = fmaf(probe[c], Wq[(size_t)c * CC + h * DD + d], a);
    red[part][d] = a;
    __syncthreads();
    if (t < DD)
        g_qhp[cs * HH * DD + h * DD + t] = red[0][t] + red[1][t] + red[2][t] + red[3][t];
}

// ================= prep 2: wk = fold(Wk,qh) -> bf16 hi/lo (rows 12-15 zeroed) ==========
__global__ __launch_bounds__(256) void k_prep_wk(const float* __restrict__ Wk,
                                                 const float* __restrict__ bq) {
    int h = blockIdx.x, sl = blockIdx.y, t = threadIdx.x;
    __shared__ float qs[DD];
    if (t < DD) {
        int i = h * DD + t;
        qs[t] = (g_qhp[i] + g_qhp[HH * DD + i] + g_qhp[2 * HH * DD + i]
               + g_qhp[3 * HH * DD + i] + bq[i]) * 0.125f;
    }
    __syncthreads();
    int base = sl * 96;
    for (int c = base + t; c < base + 96; c += 256) {
        const float4* wr = (const float4*)(Wk + (size_t)c * CC + h * DD);
        float s = 0.f;
        #pragma unroll
        for (int j = 0; j < DD / 4; j++) {
            float4 wv = wr[j];
            const float4 qv = *(const float4*)(qs + 4 * j);
            s += wv.x * qv.x + wv.y * qv.y + wv.z * qv.z + wv.w * qv.w;
        }
        __nv_bfloat16 hb = __float2bfloat16(s);
        g_wkh[h * CC + c] = hb;
        g_wkl[h * CC + c] = __float2bfloat16(s - __bfloat162float(hb));
        if (h < 4) {   // zero pad rows 12..15
            g_wkh[(HH + h) * CC + c] = __float2bfloat16(0.f);
            g_wkl[(HH + h) * CC + c] = __float2bfloat16(0.f);
        }
    }
}

// ================= prep 3: sbias[h] = qh[h,:].bk[h,:] =================
__global__ __launch_bounds__(384) void k_prep_sb(const float* __restrict__ bq,
                                                 const float* __restrict__ bk) {
    int t = threadIdx.x, h = t >> 5, lane = t & 31;
    int i1 = h * DD + lane, i2 = i1 + 32;
    float q1 = (g_qhp[i1] + g_qhp[HH * DD + i1] + g_qhp[2 * HH * DD + i1]
              + g_qhp[3 * HH * DD + i1] + bq[i1]) * 0.125f;
    float q2 = (g_qhp[i2] + g_qhp[HH * DD + i2] + g_qhp[2 * HH * DD + i2]
              + g_qhp[3 * HH * DD + i2] + bq[i2]) * 0.125f;
    float a = q1 * bk[i1] + q2 * bk[i2];
    #pragma unroll
    for (int o = 16; o; o >>= 1) a += __shfl_xor_sync(~0u, a, o);
    if (lane == 0) g_sbias[h] = a;
}

// ================= fused (mma.sync): scores MMA -> exp -> y^T MMA =================
// 512 threads, 2 blocks/SM. MMA on warps 0-7 only (A-frag dedup); all 16 warps stage.
// Phase 1: warp w owns m-tile w (16 s-rows), both head-halves (d0,d1); B hi+lo
// fused in one ldm_x4. Phase 2: OPERANDS SWAPPED — Y^T[128c,16h] = X^T . P^T:
// A = x via ldm_x4.trans (unique per warp), B = P[16h][128s] (same pattern as wk).
__global__ __launch_bounds__(512, 2) void k_fused(const float* __restrict__ x) {
    extern __shared__ __align__(16) char smem[];
    const uint32_t sb = smem_u32(smem);
    int t = threadIdx.x, w = t >> 5, lane = t & 31;
    int ch = blockIdx.x, b = blockIdx.y;
    int s0 = ch * SCHUNK;
    const float* xb = x + (size_t)b * SS * CC;
    int gid = lane >> 2, tig = lane & 3;

    if (t < 16) {
        ((float*)(smem + OFF_ZSH))[t] = 0.f;
        ((float*)(smem + OFF_SBS))[t] = (t < HH) ? g_sbias[t] : 0.f;
    }

    float d0[4] = {0.f, 0.f, 0.f, 0.f}, d1[4] = {0.f, 0.f, 0.f, 0.f};
    // phase-1 A: x rows 16w.., non-trans x4
    uint32_t xA  = sb + OFF_XH + (16 * (w & 7) + (lane & 15)) * 272 + (lane >> 4) * 16;
    uint32_t xAl = xA + (OFF_XL - OFF_XH);
    // phase-1 B fused hi+lo: lanes 0-15 hi (rows h, two k-blocks), lanes 16-31 same in lo
    uint32_t wkB0 = sb + OFF_WKH + (lane & 7) * 272 + ((lane >> 3) & 1) * 16
                  + ((lane >> 4) & 1) * (OFF_WKL - OFF_WKH);
    uint32_t wkB1 = wkB0 + 8 * 272;

    // ===== phase 1: scores over 6 c-slices of 128 =====
    for (int sl = 0; sl < 6; sl++) {
        __syncthreads();
        const float* xs = xb + (size_t)s0 * CC + sl * 128;
        #pragma unroll
        for (int j = 0; j < 8; j++) {
            int i = t + j * 512;
            int r = i >> 5, c4 = i & 31;
            float4 v = *(const float4*)(xs + (size_t)r * CC + c4 * 4);
            uint32_t h0 = pbf2(v.x, v.y), h1 = pbf2(v.z, v.w);
            float l0 = v.x - __uint_as_float(h0 << 16);
            float l1 = v.y - __uint_as_float(h0 & 0xffff0000u);
            float l2 = v.z - __uint_as_float(h1 << 16);
            float l3 = v.w - __uint_as_float(h1 & 0xffff0000u);
            *(uint2*)(smem + OFF_XH + r * 272 + c4 * 8) = make_uint2(h0, h1);
            *(uint2*)(smem + OFF_XL + r * 272 + c4 * 8) = make_uint2(pbf2(l0, l1), pbf2(l2, l3));
        }
        {   // wk slice: exactly 1 item/thread
            int h = t >> 5, c4 = t & 31;
            *(uint2*)(smem + OFF_WKH + h * 272 + c4 * 8) =
                *(const uint2*)(g_wkh + h * CC + sl * 128 + c4 * 4);
            *(uint2*)(smem + OFF_WKL + h * 272 + c4 * 8) =
                *(const uint2*)(g_wkl + h * CC + sl * 128 + c4 * 4);
        }
        __syncthreads();
        if (w < 8) {
            #pragma unroll 4
            for (int kk = 0; kk < 8; kk++) {
                uint32_t ah[4], al[4], b0[4], b1[4];
                ldm_x4(ah, xA + kk * 32);
                ldm_x4(al, xAl + kk * 32);
                ldm_x4(b0, wkB0 + kk * 32);        // {hi k0-7, hi k8-15, lo k0-7, lo k8-15}
                ldm_x4(b1, wkB1 + kk * 32);
                mma16816(d0, ah, b0);
                mma16816(d0, ah, b0 + 2);
                mma16816(d0, al, b0);
                mma16816(d1, ah, b1);
                mma16816(d1, ah, b1 + 2);
                mma16816(d1, al, b1);
            }
        }
    }

    // ===== exp + P (bf16 hi/lo, [16h][128s] stride 272B) + z =====
    if (w < 8) {
        const float* sbs = (const float*)(smem + OFF_SBS);
        int h0 = 2 * tig, r0 = 16 * w + gid;
        float e[8];
        e[0] = __expf(d0[0] + sbs[h0]);     e[1] = __expf(d0[1] + sbs[h0 + 1]);
        e[2] = __expf(d0[2] + sbs[h0]);     e[3] = __expf(d0[3] + sbs[h0 + 1]);
        e[4] = __expf(d1[0] + sbs[h0 + 8]); e[5] = __expf(d1[1] + sbs[h0 + 9]);
        e[6] = __expf(d1[2] + sbs[h0 + 8]); e[7] = __expf(d1[3] + sbs[h0 + 9]);
        #pragma unroll
        for (int k = 0; k < 8; k++) {
            int hh = (k < 4 ? h0 : h0 + 8) + (k & 1);
            int ss = r0 + ((k >> 1) & 1) * 8;
            __nv_bfloat16 hbf = __float2bfloat16(e[k]);
            float lo = e[k] - __bfloat162float(hbf);
            *(__nv_bfloat16*)(smem + OFF_PH + hh * 272 + ss * 2) = hbf;
            *(__nv_bfloat16*)(smem + OFF_PL + hh * 272 + ss * 2) = __float2bfloat16(lo);
        }
        float v0 = e[0] + e[2], v1 = e[1] + e[3], v2 = e[4] + e[6], v3 = e[5] + e[7];
        #pragma unroll
        for (int o = 4; o < 32; o <<= 1) {
            v0 += __shfl_xor_sync(~0u, v0, o);
            v1 += __shfl_xor_sync(~0u, v1, o);
            v2 += __shfl_xor_sync(~0u, v2, o);
            v3 += __shfl_xor_sync(~0u, v3, o);
        }
        if (lane < 4) {
            float* zsh = (float*)(smem + OFF_ZSH);
            atomicAdd(&zsh[2 * lane],     v0);
            atomicAdd(&zsh[2 * lane + 1], v1);
            atomicAdd(&zsh[2 * lane + 8], v2);
            atomicAdd(&zsh[2 * lane + 9], v3);
        }
    }
    __syncthreads();
    if (t < HH) g_z[(b * NCHUNK + ch) * HH + t] = ((float*)(smem + OFF_ZSH))[t];

    // ===== phase 2: Y^T[128c,16h] = X^T . P^T, REVERSE slices for L2 recency =====
    // A = X^T via x4.trans: lane addr row k = (lane&7)+((lane>>4)&1)*8,
    //                       col m(c) = 16w + ((lane>>3)&1)*8
    uint32_t xT  = sb + OFF_XH + ((lane & 7) + ((lane >> 4) & 1) * 8) * 272
                 + (16 * (w & 7) + ((lane >> 3) & 1) * 8) * 2;
    uint32_t xTl = xT + (OFF_XL - OFF_XH);
    // B = P (same pattern as wkB), fused hi+lo
    uint32_t pB0 = sb + OFF_PH + (lane & 7) * 272 + ((lane >> 3) & 1) * 16
                 + ((lane >> 4) & 1) * (OFF_PL - OFF_PH);
    uint32_t pB1 = pB0 + 8 * 272;
    float* ypb = g_ypart + (size_t)(b * NCHUNK + ch) * (HH * CC);

    for (int sl = 5; sl >= 0; sl--) {
        __syncthreads();
        const float* xs = xb + (size_t)s0 * CC + sl * 128;
        #pragma unroll
        for (int j = 0; j < 8; j++) {
            int i = t + j * 512;
            int r = i >> 5, c4 = i & 31;
            float4 v = *(const float4*)(xs + (size_t)r * CC + c4 * 4);
            uint32_t h0 = pbf2(v.x, v.y), h1 = pbf2(v.z, v.w);
            float l0 = v.x - __uint_as_float(h0 << 16);
            float l1 = v.y - __uint_as_float(h0 & 0xffff0000u);
            float l2 = v.z - __uint_as_float(h1 << 16);
            float l3 = v.w - __uint_as_float(h1 & 0xffff0000u);
            *(uint2*)(smem + OFF_XH + r * 272 + c4 * 8) = make_uint2(h0, h1);
            *(uint2*)(smem + OFF_XL + r * 272 + c4 * 8) = make_uint2(pbf2(l0, l1), pbf2(l2, l3));
        }
        __syncthreads();

        if (w < 8) {
            float dA[4] = {0.f, 0.f, 0.f, 0.f}, dB[4] = {0.f, 0.f, 0.f, 0.f};
            #pragma unroll 4
            for (int kk = 0; kk < 8; kk++) {
                uint32_t ah[4], al[4], b0[4], b1[4];
                ldm_x4t(ah, xT + kk * 16 * 272);
                ldm_x4t(al, xTl + kk * 16 * 272);
                ldm_x4(b0, pB0 + kk * 32);
                ldm_x4(b1, pB1 + kk * 32);
                mma16816(dA, ah, b0);
                mma16816(dA, ah, b0 + 2);
                mma16816(dA, al, b0);
                mma16816(dB, ah, b1);
                mma16816(dB, ah, b1 + 2);
                mma16816(dB, al, b1);
            }
            // store: rows = c, cols = h
            int c0 = sl * 128 + 16 * (w & 7);
            int h0 = 2 * tig;
            ypb[(size_t)h0 * CC + c0 + gid]           = dA[0];
            ypb[(size_t)(h0 + 1) * CC + c0 + gid]     = dA[1];
            ypb[(size_t)h0 * CC + c0 + gid + 8]       = dA[2];
            ypb[(size_t)(h0 + 1) * CC + c0 + gid + 8] = dA[3];
            if (h0 + 8 < HH) {
                ypb[(size_t)(h0 + 8) * CC + c0 + gid]     = dB[0];
                ypb[(size_t)(h0 + 8) * CC + c0 + gid + 8] = dB[2];
            }
            if (h0 + 9 < HH) {
                ypb[(size_t)(h0 + 9) * CC + c0 + gid]     = dB[1];
                ypb[(size_t)(h0 + 9) * CC + c0 + gid + 8] = dB[3];
            }
        }
    }
}

// ================= combine + ctx (FROZEN round-7 version) =================
__global__ __launch_bounds__(256) void k_combctx(const float* __restrict__ Wv,
                                                 const float* __restrict__ bv) {
    int b = blockIdx.x, h = blockIdx.y, t = threadIdx.x;
    __shared__ float ys[CC];
    __shared__ float red[4][DD];
    __shared__ float invZ_s;

    if (t < 32) {
        float z = 0.f;
        for (int c2 = t; c2 < NCHUNK; c2 += 32) z += g_z[(b * NCHUNK + c2) * HH + h];
        #pragma unroll
        for (int o = 16; o; o >>= 1) z += __shfl_xor_sync(~0u, z, o);
        if (t == 0) invZ_s = 1.f / z;
    }
    __syncthreads();
    float invZ = invZ_s;

    #pragma unroll
    for (int i = 0; i < 3; i++) {
        int c = t + 256 * i;
        const float* base = g_ypart + (size_t)b * NCHUNK * HH * CC + h * CC + c;
        float a0 = 0.f, a1 = 0.f, a2 = 0.f, a3 = 0.f;
        #pragma unroll 4
        for (int chn = 0; chn < NCHUNK - 3; chn += 4) {
            a0 += base[(size_t)chn * HH * CC];
            a1 += base[(size_t)(chn + 1) * HH * CC];
            a2 += base[(size_t)(chn + 2) * HH * CC];
            a3 += base[(size_t)(chn + 3) * HH * CC];
        }
        for (int chn = NCHUNK & ~3; chn < NCHUNK; chn++)
            a0 += base[(size_t)chn * HH * CC];
        ys[c] = ((a0 + a1) + (a2 + a3)) * invZ;
    }
    __syncthreads();

    int d = t & 63, part = t >> 6;
    const float* wp = Wv + h * DD + d;
    float a0 = 0.f, a1 = 0.f;
    #pragma unroll 8
    for (int c = part; c < CC; c += 8) {
        a0 = fmaf(ys[c],     wp[(size_t)c * CC],       a0);
        a1 = fmaf(ys[c + 4], wp[(size_t)(c + 4) * CC], a1);
    }
    red[part][d] = a0 + a1;
    __syncthreads();
    if (t < DD)
        g_ctx[b * CC + h * DD + t] =
            red[0][t] + red[1][t] + red[2][t] + red[3][t] + bv[h * DD + t];
}

// ================= out (FROZEN round-7 version) =================
__global__ __launch_bounds__(192) void k_out(const float* __restrict__ Wo,
                                             const float* __restrict__ bo,
                                             float* __restrict__ out) {
    int b = blockIdx.x, part = blockIdx.y, t = threadIdx.x;
    __shared__ float cs[CC];
    for (int i = t; i < CC; i += 192) cs[i] = g_ctx[b * CC + i];
    __syncthreads();
    int cp = part * 192 + t;
    const float* wp = Wo + cp;
    float a0 = 0.f, a1 = 0.f, a2 = 0.f, a3 = 0.f;
    #pragma unroll 8
    for (int o = 0; o < CC; o += 4) {
        a0 = fmaf(cs[o],     wp[(size_t)o * CC],       a0);
        a1 = fmaf(cs[o + 1], wp[(size_t)(o + 1) * CC], a1);
        a2 = fmaf(cs[o + 2], wp[(size_t)(o + 2) * CC], a2);
        a3 = fmaf(cs[o + 3], wp[(size_t)(o + 3) * CC], a3);
    }
    out[(size_t)b * CC + cp] = (a0 + a1) + (a2 + a3) + bo[cp];
}

extern "C" void kernel_launch(void* const* d_in, const int* in_sizes, int n_in,
                              void* d_out, int out_size) {
    const float* x     = (const float*)d_in[0];
    const float* probe = (const float*)d_in[1];
    const float* Wq    = (const float*)d_in[2];
    const float* bq    = (const float*)d_in[3];
    const float* Wk    = (const float*)d_in[4];
    const float* bk    = (const float*)d_in[5];
    const float* Wv    = (const float*)d_in[6];
    const float* bv    = (const float*)d_in[7];
    const float* Wo    = (const float*)d_in[8];
    const float* bo    = (const float*)d_in[9];
    float* out = (float*)d_out;

    cudaFuncSetAttribute(k_fused, cudaFuncAttributeMaxDynamicSharedMemorySize, SMEM_TOTAL);

    k_prep_qh<<<dim3(HH, 4), 256>>>(probe, Wq);             // #1
    k_prep_wk<<<dim3(HH, 8), 256>>>(Wk, bq);                // #2
    k_prep_sb<<<1, 384>>>(bq, bk);                          // #3
    k_fused<<<dim3(NCHUNK, BB), 512, SMEM_TOTAL>>>(x);      // #4  <- profiled slot
    k_combctx<<<dim3(BB, HH), 256>>>(Wv, bv);               // #5
    k_out<<<dim3(BB, 4), 192>>>(Wo, bo, out);               // #6
}